// round 13
// baseline (speedup 1.0000x reference)
#include <cuda_runtime.h>
#include <cuda_bf16.h>
#include <math.h>
#include <stdint.h>

#define D 256
#define HH 512
#define MR1 128          // gemm1 rows per CTA
#define NT1 512
#define MR2 64           // gemm2 rows per CTA
#define NT2 256
#define MAX_NODES 65536
#define MAX_LVL 16384

// ---------------- device scratch ----------------
__device__ float g_embeds[MAX_NODES * D];
__device__ __nv_bfloat16 g_embh[MAX_NODES * D];
__device__ __nv_bfloat16 g_embl[MAX_NODES * D];
__device__ __nv_bfloat16 g_oph[16 * D], g_opl[16 * D];
__device__ int   g_list[6][MAX_LVL];
__device__ int   g_cnt[6];
__device__ __nv_bfloat16 g_W1bTh[HH * 768],  g_W1bTl[HH * 768];
__device__ __nv_bfloat16 g_W1tTh[HH * 1024], g_W1tTl[HH * 1024];
__device__ __nv_bfloat16 g_W2bTh[D * HH],    g_W2bTl[D * HH];
__device__ __nv_bfloat16 g_W2tTh[D * HH],    g_W2tTl[D * HH];
__device__ __nv_bfloat16 g_hh[2 * MAX_LVL * HH];
__device__ __nv_bfloat16 g_hl[2 * MAX_LVL * HH];

// ---------------- helpers ----------------
__device__ __forceinline__ uint32_t bfpack(float a, float b) {
    __nv_bfloat162 t = __floats2bfloat162_rn(a, b);
    return *reinterpret_cast<uint32_t*>(&t);
}
__device__ __forceinline__ float bfres(float a) {
    return a - __bfloat162float(__float2bfloat16_rn(a));
}
__device__ __forceinline__ float gelu_exact(float x) {
    return 0.5f * x * (1.0f + erff(x * 0.70710678118654752440f));
}
__device__ __forceinline__ void ldsm4(uint32_t r[4], uint32_t addr) {
    asm volatile("ldmatrix.sync.aligned.m8n8.x4.shared.b16 {%0,%1,%2,%3}, [%4];"
                 : "=r"(r[0]), "=r"(r[1]), "=r"(r[2]), "=r"(r[3]) : "r"(addr));
}
__device__ __forceinline__ void mma16816(float c[4], const uint32_t a[4],
                                         uint32_t b0, uint32_t b1) {
    asm volatile(
        "mma.sync.aligned.m16n8k16.row.col.f32.bf16.bf16.f32 "
        "{%0,%1,%2,%3}, {%4,%5,%6,%7}, {%8,%9}, {%0,%1,%2,%3};"
        : "+f"(c[0]), "+f"(c[1]), "+f"(c[2]), "+f"(c[3])
        : "r"(a[0]), "r"(a[1]), "r"(a[2]), "r"(a[3]), "r"(b0), "r"(b1));
}
__device__ __forceinline__ void cpasync16(uint32_t dst, const void* src) {
    asm volatile("cp.async.cg.shared.global [%0], [%1], 16;" :: "r"(dst), "l"(src));
}
#define CP_COMMIT() asm volatile("cp.async.commit_group;" ::: "memory")
#define CP_WAIT0()  asm volatile("cp.async.wait_group 0;" ::: "memory")

// ---------------- gemm1 smem layout (NT=512, M=128) ----------------
#define G1_PTRH 0
#define G1_PTRL 4096
#define G1_POOL 8192
#define G1_BUF  61440
#define G1_AH(b) (G1_POOL + (b) * G1_BUF)          // 128 x 80
#define G1_AL(b) (G1_AH(b) + 10240)
#define G1_BH(b) (G1_AH(b) + 20480)                // 256 x 80
#define G1_BL(b) (G1_AH(b) + 40960)
#define G1_SMEM (G1_POOL + 2 * G1_BUF)             // 131072

// ---------------- gemm2 smem layout (NT=256, M=64) ----------------
#define G2_PTRF  0
#define G2_NODE  2048
#define G2_IDX   2304
#define G2_VALID 2560
#define G2_MU    2816
#define G2_RS    3072
#define G2_POOL  4096
#define G2_BUF   51200
#define G2_AH(b) (G2_POOL + (b) * G2_BUF)
#define G2_AL(b) (G2_AH(b) + 5120)
#define G2_BH(b) (G2_AH(b) + 10240)
#define G2_BL(b) (G2_AH(b) + 30720)
#define G2_PZ    G2_POOL
#define G2_SMEM (G2_POOL + 2 * G2_BUF)             // 106496

// ---------------- pre-kernels ----------------
__global__ void convall_kernel(const float* __restrict__ W1b, const float* __restrict__ W1t,
                               const float* __restrict__ W2b, const float* __restrict__ W2t) {
    __shared__ float tile[32][33];
    int bx = blockIdx.x;
    if (bx == 0 && threadIdx.y == 0 && threadIdx.x < 6) g_cnt[threadIdx.x] = 0;
    const float* in;
    __nv_bfloat16 *oh, *ol;
    int K, C, local;
    if (bx < 384)        { in = W1b; oh = g_W1bTh; ol = g_W1bTl; K = 768;  C = 512; local = bx; }
    else if (bx < 896)   { in = W1t; oh = g_W1tTh; ol = g_W1tTl; K = 1024; C = 512; local = bx - 384; }
    else if (bx < 1024)  { in = W2b; oh = g_W2bTh; ol = g_W2bTl; K = 512;  C = 256; local = bx - 896; }
    else                 { in = W2t; oh = g_W2tTh; ol = g_W2tTl; K = 512;  C = 256; local = bx - 1024; }
    int ktiles = K >> 5;
    int kt = local % ktiles, ct = local / ktiles;
    int k0 = kt * 32, c0 = ct * 32;
    int tx = threadIdx.x, ty = threadIdx.y;
    #pragma unroll
    for (int r = 0; r < 32; r += 8)
        tile[ty + r][tx] = in[(size_t)(k0 + ty + r) * C + c0 + tx];
    __syncthreads();
    #pragma unroll
    for (int r = 0; r < 32; r += 8) {
        float f = tile[tx][ty + r];
        __nv_bfloat16 h = __float2bfloat16_rn(f);
        float fl = f - __bfloat162float(h);
        size_t o = (size_t)(c0 + ty + r) * K + k0 + tx;
        oh[o] = h;
        ol[o] = __float2bfloat16_rn(fl);
    }
}

__global__ void init_all_kernel(const int* __restrict__ comp_ids,
                                const float* __restrict__ comp_table,
                                const float* __restrict__ op_table, int n_nodes) {
    int b = blockIdx.x, c = threadIdx.x;
    if (b < n_nodes) {
        float f = comp_table[comp_ids[b] * D + c];
        __nv_bfloat16 h = __float2bfloat16_rn(f);
        g_embeds[b * D + c] = f;
        g_embh[b * D + c] = h;
        g_embl[b * D + c] = __float2bfloat16_rn(f - __bfloat162float(h));
    } else {
        int row = b - n_nodes;
        float f = op_table[row * D + c];
        __nv_bfloat16 h = __float2bfloat16_rn(f);
        g_oph[row * D + c] = h;
        g_opl[row * D + c] = __float2bfloat16_rn(f - __bfloat162float(h));
    }
}

__global__ void compact_kernel(const int* __restrict__ lvl2, int n2,
                               const int* __restrict__ lvl1, int n1,
                               const int* __restrict__ lvl0, int n0,
                               const int* __restrict__ third) {
    int i = blockIdx.x * blockDim.x + threadIdx.x;
    int lvl, j;
    const int* idx;
    if (i < n2)                { lvl = 0; j = i;            idx = lvl2; }
    else if (i < n2 + n1)      { lvl = 1; j = i - n2;       idx = lvl1; }
    else if (i < n2 + n1 + n0) { lvl = 2; j = i - n2 - n1;  idx = lvl0; }
    else return;
    int node = idx[j];
    bool tern = (third[node] >= 0);
    int slot = lvl * 2 + (tern ? 0 : 1);
    int pos = atomicAdd(&g_cnt[slot], 1);
    g_list[slot][pos] = j;
}

// ---------------- GEMM1: h = gelu(x @ W1 + b1) -> global hi/lo ----------------
// grid: nb128 * 4 (bit0 = nsplit, bit1 = slotbit, rest = tile); NT=512, M=128
__global__ __launch_bounds__(NT1, 1)
void gemm1_kernel(int lvl,
                  const int* __restrict__ lvl_idx,
                  const int* __restrict__ lc, const int* __restrict__ rc,
                  const int* __restrict__ tcld,
                  const int* __restrict__ opids,
                  const __nv_bfloat16* __restrict__ W1bTh, const __nv_bfloat16* __restrict__ W1bTl,
                  const __nv_bfloat16* __restrict__ W1tTh, const __nv_bfloat16* __restrict__ W1tTl,
                  const float* __restrict__ b1b, const float* __restrict__ b1t) {
    extern __shared__ char smem[];
    int bx = blockIdx.x;
    int nsplit = bx & 1;
    int tern = ((bx >> 1) & 1) ? 0 : 1;
    int tile = bx >> 2;
    int slot = lvl * 2 + (tern ? 0 : 1);
    int cnt = g_cnt[slot];
    int base = tile * MR1;
    if (base >= cnt) return;

    const int K1 = tern ? 1024 : 768;
    const __nv_bfloat16* WTh = tern ? W1tTh : W1bTh;
    const __nv_bfloat16* WTl = tern ? W1tTl : W1bTl;
    const float* b1 = tern ? b1t : b1b;
    size_t hoff = (size_t)(tern ? 0 : MAX_LVL);

    int t = threadIdx.x;
    int lane = t & 31, wid = t >> 5;
    uint32_t sb = (uint32_t)__cvta_generic_to_shared(smem);

    uint64_t* sm_ptrh = (uint64_t*)(smem + G1_PTRH);
    uint64_t* sm_ptrl = (uint64_t*)(smem + G1_PTRL);

    const int* rows = g_list[slot];
    if (t < MR1) {
        int rr = min(base + t, cnt - 1);
        int i = rows[rr];
        int node = lvl_idx[i];
        size_t oo = (size_t)opids[node] * D;
        size_t lo_ = (size_t)lc[node] * D;
        size_t ro_ = (size_t)rc[node] * D;
        size_t to_ = tern ? (size_t)tcld[node] * D : lo_;
        sm_ptrh[t * 4 + 0] = (uint64_t)(g_oph + oo);
        sm_ptrh[t * 4 + 1] = (uint64_t)(g_embh + lo_);
        sm_ptrh[t * 4 + 2] = (uint64_t)(g_embh + ro_);
        sm_ptrh[t * 4 + 3] = (uint64_t)(g_embh + to_);
        sm_ptrl[t * 4 + 0] = (uint64_t)(g_opl + oo);
        sm_ptrl[t * 4 + 1] = (uint64_t)(g_embl + lo_);
        sm_ptrl[t * 4 + 2] = (uint64_t)(g_embl + ro_);
        sm_ptrl[t * 4 + 3] = (uint64_t)(g_embl + to_);
    }
    __syncthreads();

    int wm = wid & 3, wn = wid >> 2;       // 4 m-warps x 4 n-warps
    int m0 = wm * 32;
    int laneA_row  = lane & 15;
    int laneA_koff = (lane >> 4) * 16;
    int laneB_nrow = (lane & 7) + ((lane & 16) >> 1);
    int laneB_koff = ((lane >> 3) & 1) * 16;

    int a_row = t >> 2, a_q = t & 3;       // A: 128 rows x 1x16B per plane
    int b_r = t >> 1, b_half = t & 1;      // B: 256 rows; each thread 32 contiguous bytes

    float c1[2][8][4];
    #pragma unroll
    for (int i = 0; i < 2; i++)
        #pragma unroll
        for (int j = 0; j < 8; j++)
            #pragma unroll
            for (int r = 0; r < 4; r++) c1[i][j][r] = 0.0f;

    int nkc = K1 >> 5;

    // prologue chunk 0
    {
        const char* srcH = (const char*)sm_ptrh[a_row * 4 + 0] + a_q * 16;
        const char* srcL = (const char*)sm_ptrl[a_row * 4 + 0] + a_q * 16;
        cpasync16(sb + G1_AH(0) + a_row * 80 + a_q * 16, srcH);
        cpasync16(sb + G1_AL(0) + a_row * 80 + a_q * 16, srcL);
        // B: thread covers bytes [b_half*32, b_half*32+32) of the 64B row chunk
        const char* wsH = (const char*)(WTh + (size_t)(nsplit * 256 + b_r) * K1 + b_half * 16);
        const char* wsL = (const char*)(WTl + (size_t)(nsplit * 256 + b_r) * K1 + b_half * 16);
        uint32_t eH = sb + G1_BH(0) + b_r * 80 + b_half * 32;
        uint32_t eL = sb + G1_BL(0) + b_r * 80 + b_half * 32;
        cpasync16(eH, wsH); cpasync16(eH + 16, wsH + 16);
        cpasync16(eL, wsL); cpasync16(eL + 16, wsL + 16);
        CP_COMMIT();
    }
    for (int kc = 0; kc < nkc; kc++) {
        CP_WAIT0();
        __syncthreads();
        if (kc + 1 < nkc) {
            int buf = (kc + 1) & 1;
            int k0 = (kc + 1) * 32, seg = k0 >> 8;
            int sob = (k0 & 255) * 2 + a_q * 16;
            const char* srcH = (const char*)sm_ptrh[a_row * 4 + seg] + sob;
            const char* srcL = (const char*)sm_ptrl[a_row * 4 + seg] + sob;
            cpasync16(sb + G1_AH(buf) + a_row * 80 + a_q * 16, srcH);
            cpasync16(sb + G1_AL(buf) + a_row * 80 + a_q * 16, srcL);
            const char* wsH = (const char*)(WTh + (size_t)(nsplit * 256 + b_r) * K1 + k0 + b_half * 16);
            const char* wsL = (const char*)(WTl + (size_t)(nsplit * 256 + b_r) * K1 + k0 + b_half * 16);
            uint32_t eH = sb + G1_BH(buf) + b_r * 80 + b_half * 32;
            uint32_t eL = sb + G1_BL(buf) + b_r * 80 + b_half * 32;
            cpasync16(eH, wsH); cpasync16(eH + 16, wsH + 16);
            cpasync16(eL, wsL); cpasync16(eL + 16, wsL + 16);
            CP_COMMIT();
        }
        int buf = kc & 1;
        uint32_t AHp = G1_AH(buf), ALp = G1_AL(buf), BHp = G1_BH(buf), BLp = G1_BL(buf);
        #pragma unroll
        for (int ks = 0; ks < 2; ks++) {
            int kb = ks * 32;
            uint32_t ah0[4], ah1[4], al0[4], al1[4];
            ldsm4(ah0, sb + AHp + (m0 + laneA_row) * 80 + kb + laneA_koff);
            ldsm4(ah1, sb + AHp + (m0 + 16 + laneA_row) * 80 + kb + laneA_koff);
            ldsm4(al0, sb + ALp + (m0 + laneA_row) * 80 + kb + laneA_koff);
            ldsm4(al1, sb + ALp + (m0 + 16 + laneA_row) * 80 + kb + laneA_koff);
            #pragma unroll
            for (int g = 0; g < 2; g++) {
                int ng = wn * 64 + g * 32;
                int jb = g * 4;
                uint32_t bh0[4], bh1[4], bl0[4], bl1[4];
                ldsm4(bh0, sb + BHp + (ng + laneB_nrow) * 80 + kb + laneB_koff);
                ldsm4(bh1, sb + BHp + (ng + 16 + laneB_nrow) * 80 + kb + laneB_koff);
                mma16816(c1[0][jb + 0], ah0, bh0[0], bh0[1]);
                mma16816(c1[0][jb + 1], ah0, bh0[2], bh0[3]);
                mma16816(c1[0][jb + 2], ah0, bh1[0], bh1[1]);
                mma16816(c1[0][jb + 3], ah0, bh1[2], bh1[3]);
                mma16816(c1[1][jb + 0], ah1, bh0[0], bh0[1]);
                mma16816(c1[1][jb + 1], ah1, bh0[2], bh0[3]);
                mma16816(c1[1][jb + 2], ah1, bh1[0], bh1[1]);
                mma16816(c1[1][jb + 3], ah1, bh1[2], bh1[3]);
                ldsm4(bl0, sb + BLp + (ng + laneB_nrow) * 80 + kb + laneB_koff);
                ldsm4(bl1, sb + BLp + (ng + 16 + laneB_nrow) * 80 + kb + laneB_koff);
                mma16816(c1[0][jb + 0], ah0, bl0[0], bl0[1]);
                mma16816(c1[0][jb + 1], ah0, bl0[2], bl0[3]);
                mma16816(c1[0][jb + 2], ah0, bl1[0], bl1[1]);
                mma16816(c1[0][jb + 3], ah0, bl1[2], bl1[3]);
                mma16816(c1[1][jb + 0], ah1, bl0[0], bl0[1]);
                mma16816(c1[1][jb + 1], ah1, bl0[2], bl0[3]);
                mma16816(c1[1][jb + 2], ah1, bl1[0], bl1[1]);
                mma16816(c1[1][jb + 3], ah1, bl1[2], bl1[3]);
                mma16816(c1[0][jb + 0], al0, bh0[0], bh0[1]);
                mma16816(c1[0][jb + 1], al0, bh0[2], bh0[3]);
                mma16816(c1[0][jb + 2], al0, bh1[0], bh1[1]);
                mma16816(c1[0][jb + 3], al0, bh1[2], bh1[3]);
                mma16816(c1[1][jb + 0], al1, bh0[0], bh0[1]);
                mma16816(c1[1][jb + 1], al1, bh0[2], bh0[3]);
                mma16816(c1[1][jb + 2], al1, bh1[0], bh1[1]);
                mma16816(c1[1][jb + 3], al1, bh1[2], bh1[3]);
            }
        }
    }

    // epilogue: bias + gelu -> global h hi/lo
    {
        #pragma unroll
        for (int j = 0; j < 8; j++) {
            int ncol = wn * 64 + j * 8 + (lane & 3) * 2;
            int gcol = nsplit * 256 + ncol;
            float2 bb = *(const float2*)(b1 + gcol);
            #pragma unroll
            for (int i = 0; i < 2; i++) {
                int r0 = m0 + i * 16 + (lane >> 2);
                size_t gr0 = (hoff + base + r0) * HH + gcol;
                size_t gr1 = (hoff + base + r0 + 8) * HH + gcol;
                float h0 = gelu_exact(c1[i][j][0] + bb.x);
                float h1 = gelu_exact(c1[i][j][1] + bb.y);
                *(uint32_t*)(g_hh + gr0) = bfpack(h0, h1);
                *(uint32_t*)(g_hl + gr0) = bfpack(bfres(h0), bfres(h1));
                float h2 = gelu_exact(c1[i][j][2] + bb.x);
                float h3 = gelu_exact(c1[i][j][3] + bb.y);
                *(uint32_t*)(g_hh + gr1) = bfpack(h2, h3);
                *(uint32_t*)(g_hl + gr1) = bfpack(bfres(h2), bfres(h3));
            }
        }
    }
}

// ---------------- GEMM2: y = h @ W2 + b2; residual + LN ----------------
__global__ __launch_bounds__(NT2, 2)
void gemm2_kernel(int lvl,
                  const int* __restrict__ lvl_idx,
                  const int* __restrict__ lc, const int* __restrict__ rc,
                  const int* __restrict__ tcld,
                  const __nv_bfloat16* __restrict__ W2bTh, const __nv_bfloat16* __restrict__ W2bTl,
                  const __nv_bfloat16* __restrict__ W2tTh, const __nv_bfloat16* __restrict__ W2tTl,
                  const float* __restrict__ b2b, const float* __restrict__ b2t,
                  const float* __restrict__ gma, const float* __restrict__ bta,
                  float* __restrict__ final_out) {
    extern __shared__ char smem[];
    int bx = blockIdx.x;
    int tern = (bx & 1) ? 0 : 1;
    int tile = bx >> 1;
    int slot = lvl * 2 + (tern ? 0 : 1);
    int cnt = g_cnt[slot];
    int base = tile * MR2;
    if (base >= cnt) return;

    const __nv_bfloat16* WTh = tern ? W2tTh : W2bTh;
    const __nv_bfloat16* WTl = tern ? W2tTl : W2bTl;
    const float* b2 = tern ? b2t : b2b;
    size_t hoff = (size_t)(tern ? 0 : MAX_LVL);

    int t = threadIdx.x;
    int lane = t & 31, wid = t >> 5;
    uint32_t sb = (uint32_t)__cvta_generic_to_shared(smem);

    uint64_t* sm_ptrf = (uint64_t*)(smem + G2_PTRF);
    int* sm_node  = (int*)(smem + G2_NODE);
    int* sm_idx   = (int*)(smem + G2_IDX);
    int* sm_valid = (int*)(smem + G2_VALID);
    float* sm_mu  = (float*)(smem + G2_MU);
    float* sm_rs  = (float*)(smem + G2_RS);

    const int* rows = g_list[slot];
    if (t < MR2) {
        int rr = min(base + t, cnt - 1);
        int i = rows[rr];
        int node = lvl_idx[i];
        sm_node[t] = node;
        sm_idx[t] = i;
        sm_valid[t] = (base + t < cnt) ? 1 : 0;
        size_t lo_ = (size_t)lc[node] * D;
        size_t ro_ = (size_t)rc[node] * D;
        size_t to_ = tern ? (size_t)tcld[node] * D : lo_;
        sm_ptrf[t * 4 + 1] = (uint64_t)(g_embeds + lo_);
        sm_ptrf[t * 4 + 2] = (uint64_t)(g_embeds + ro_);
        sm_ptrf[t * 4 + 3] = (uint64_t)(g_embeds + to_);
    }
    __syncthreads();

    int wm = wid & 1, wn = wid >> 1;
    int m0 = wm * 32;
    int laneA_row  = lane & 15;
    int laneA_koff = (lane >> 4) * 16;
    int laneB_nrow = (lane & 7) + ((lane & 16) >> 1);
    int laneB_koff = ((lane >> 3) & 1) * 16;

    int a_row = t >> 2, a_q = t & 3;

    float c2[2][8][4];
    #pragma unroll
    for (int i = 0; i < 2; i++)
        #pragma unroll
        for (int j = 0; j < 8; j++)
            #pragma unroll
            for (int r = 0; r < 4; r++) c2[i][j][r] = 0.0f;

    // prologue chunk 0
    {
        const char* srcH = (const char*)(g_hh + (hoff + base + a_row) * HH) + a_q * 16;
        const char* srcL = (const char*)(g_hl + (hoff + base + a_row) * HH) + a_q * 16;
        cpasync16(sb + G2_AH(0) + a_row * 80 + a_q * 16, srcH);
        cpasync16(sb + G2_AL(0) + a_row * 80 + a_q * 16, srcL);
        const char* wsH = (const char*)(WTh + (size_t)t * HH);
        const char* wsL = (const char*)(WTl + (size_t)t * HH);
        uint32_t eH = sb + G2_BH(0) + t * 80;
        uint32_t eL = sb + G2_BL(0) + t * 80;
        #pragma unroll
        for (int j = 0; j < 4; j++) cpasync16(eH + j * 16, wsH + j * 16);
        #pragma unroll
        for (int j = 0; j < 4; j++) cpasync16(eL + j * 16, wsL + j * 16);
        CP_COMMIT();
    }
    for (int kc = 0; kc < 16; kc++) {
        CP_WAIT0();
        __syncthreads();
        if (kc + 1 < 16) {
            int buf = (kc + 1) & 1;
            int k0 = (kc + 1) * 32;
            const char* srcH = (const char*)(g_hh + (hoff + base + a_row) * HH + k0) + a_q * 16;
            const char* srcL = (const char*)(g_hl + (hoff + base + a_row) * HH + k0) + a_q * 16;
            cpasync16(sb + G2_AH(buf) + a_row * 80 + a_q * 16, srcH);
            cpasync16(sb + G2_AL(buf) + a_row * 80 + a_q * 16, srcL);
            const char* wsH = (const char*)(WTh + (size_t)t * HH + k0);
            const char* wsL = (const char*)(WTl + (size_t)t * HH + k0);
            uint32_t eH = sb + G2_BH(buf) + t * 80;
            uint32_t eL = sb + G2_BL(buf) + t * 80;
            #pragma unroll
            for (int j = 0; j < 4; j++) cpasync16(eH + j * 16, wsH + j * 16);
            #pragma unroll
            for (int j = 0; j < 4; j++) cpasync16(eL + j * 16, wsL + j * 16);
            CP_COMMIT();
        }
        int buf = kc & 1;
        uint32_t AHp = G2_AH(buf), ALp = G2_AL(buf), BHp = G2_BH(buf), BLp = G2_BL(buf);
        #pragma unroll
        for (int ks = 0; ks < 2; ks++) {
            int kb = ks * 32;
            uint32_t ah0[4], ah1[4], al0[4], al1[4];
            ldsm4(ah0, sb + AHp + (m0 + laneA_row) * 80 + kb + laneA_koff);
            ldsm4(ah1, sb + AHp + (m0 + 16 + laneA_row) * 80 + kb + laneA_koff);
            ldsm4(al0, sb + ALp + (m0 + laneA_row) * 80 + kb + laneA_koff);
            ldsm4(al1, sb + ALp + (m0 + 16 + laneA_row) * 80 + kb + laneA_koff);
            #pragma unroll
            for (int g = 0; g < 2; g++) {
                int ng = wn * 64 + g * 32;
                int jb = g * 4;
                uint32_t bh0[4], bh1[4], bl0[4], bl1[4];
                ldsm4(bh0, sb + BHp + (ng + laneB_nrow) * 80 + kb + laneB_koff);
                ldsm4(bh1, sb + BHp + (ng + 16 + laneB_nrow) * 80 + kb + laneB_koff);
                mma16816(c2[0][jb + 0], ah0, bh0[0], bh0[1]);
                mma16816(c2[0][jb + 1], ah0, bh0[2], bh0[3]);
                mma16816(c2[0][jb + 2], ah0, bh1[0], bh1[1]);
                mma16816(c2[0][jb + 3], ah0, bh1[2], bh1[3]);
                mma16816(c2[1][jb + 0], ah1, bh0[0], bh0[1]);
                mma16816(c2[1][jb + 1], ah1, bh0[2], bh0[3]);
                mma16816(c2[1][jb + 2], ah1, bh1[0], bh1[1]);
                mma16816(c2[1][jb + 3], ah1, bh1[2], bh1[3]);
                ldsm4(bl0, sb + BLp + (ng + laneB_nrow) * 80 + kb + laneB_koff);
                ldsm4(bl1, sb + BLp + (ng + 16 + laneB_nrow) * 80 + kb + laneB_koff);
                mma16816(c2[0][jb + 0], ah0, bl0[0], bl0[1]);
                mma16816(c2[0][jb + 1], ah0, bl0[2], bl0[3]);
                mma16816(c2[0][jb + 2], ah0, bl1[0], bl1[1]);
                mma16816(c2[0][jb + 3], ah0, bl1[2], bl1[3]);
                mma16816(c2[1][jb + 0], ah1, bl0[0], bl0[1]);
                mma16816(c2[1][jb + 1], ah1, bl0[2], bl0[3]);
                mma16816(c2[1][jb + 2], ah1, bl1[0], bl1[1]);
                mma16816(c2[1][jb + 3], ah1, bl1[2], bl1[3]);
                mma16816(c2[0][jb + 0], al0, bh0[0], bh0[1]);
                mma16816(c2[0][jb + 1], al0, bh0[2], bh0[3]);
                mma16816(c2[0][jb + 2], al0, bh1[0], bh1[1]);
                mma16816(c2[0][jb + 3], al0, bh1[2], bh1[3]);
                mma16816(c2[1][jb + 0], al1, bh0[0], bh0[1]);
                mma16816(c2[1][jb + 1], al1, bh0[2], bh0[3]);
                mma16816(c2[1][jb + 2], al1, bh1[0], bh1[1]);
                mma16816(c2[1][jb + 3], al1, bh1[2], bh1[3]);
            }
        }
    }
    __syncthreads();

    // epilogue: bias + residual -> zbuf
    {
        #pragma unroll
        for (int i = 0; i < 2; i++) {
            #pragma unroll
            for (int rh = 0; rh < 2; rh++) {
                int m = m0 + i * 16 + rh * 8 + (lane >> 2);
                const float* lp = (const float*)sm_ptrf[m * 4 + 1];
                const float* rp = (const float*)sm_ptrf[m * 4 + 2];
                const float* tp = (const float*)sm_ptrf[m * 4 + 3];
                #pragma unroll
                for (int j = 0; j < 8; j++) {
                    int n = wn * 64 + j * 8 + (lane & 3) * 2;
                    float2 bv = *(const float2*)(b2 + n);
                    float y0 = c2[i][j][rh * 2]     + bv.x;
                    float y1 = c2[i][j][rh * 2 + 1] + bv.y;
                    float2 lv = *(const float2*)(lp + n);
                    float2 rv = *(const float2*)(rp + n);
                    if (tern) {
                        float2 tv = *(const float2*)(tp + n);
                        y0 += (lv.x + rv.x + tv.x) * (1.0f / 3.0f);
                        y1 += (lv.y + rv.y + tv.y) * (1.0f / 3.0f);
                    } else {
                        y0 += lv.x + rv.x;
                        y1 += lv.y + rv.y;
                    }
                    *(float2*)(smem + G2_PZ + m * 1040 + n * 4) = make_float2(y0, y1);
                }
            }
        }
    }
    __syncthreads();

    if (t < MR2) {
        const float* zr = (const float*)(smem + G2_PZ + t * 1040);
        float s = 0.0f, s2 = 0.0f;
        #pragma unroll 8
        for (int c = 0; c < D; c++) {
            float v = zr[c];
            s += v;
            s2 += v * v;
        }
        float mu = s * (1.0f / 256.0f);
        float var = s2 * (1.0f / 256.0f) - mu * mu;
        sm_mu[t] = mu;
        sm_rs[t] = rsqrtf(var + 1e-5f);
    }
    __syncthreads();

    for (int idx = t; idx < MR2 * 64; idx += NT2) {
        int row = idx >> 6, q = idx & 63;
        if (!sm_valid[row]) continue;
        float mu = sm_mu[row], rs = sm_rs[row];
        const float* zr = (const float*)(smem + G2_PZ + row * 1040) + q * 4;
        float4 g4 = *(const float4*)(gma + q * 4);
        float4 be = *(const float4*)(bta + q * 4);
        float4 o;
        o.x = (zr[0] - mu) * rs * g4.x + be.x;
        o.y = (zr[1] - mu) * rs * g4.y + be.y;
        o.z = (zr[2] - mu) * rs * g4.z + be.z;
        o.w = (zr[3] - mu) * rs * g4.w + be.w;
        if (final_out) {
            *(float4*)(final_out + (size_t)sm_idx[row] * D + q * 4) = o;
        } else {
            size_t off = (size_t)sm_node[row] * D + q * 4;
            *(float4*)(g_embeds + off) = o;
            uint2 hv, lv;
            hv.x = bfpack(o.x, o.y);
            hv.y = bfpack(o.z, o.w);
            lv.x = bfpack(bfres(o.x), bfres(o.y));
            lv.y = bfpack(bfres(o.z), bfres(o.w));
            *(uint2*)(g_embh + off) = hv;
            *(uint2*)(g_embl + off) = lv;
        }
    }
}

// ---------------- launcher ----------------
extern "C" void kernel_launch(void* const* d_in, const int* in_sizes, int n_in,
                              void* d_out, int out_size) {
    const int*   comp_ids   = (const int*)d_in[0];
    const int*   op_ids     = (const int*)d_in[1];
    const int*   lc         = (const int*)d_in[2];
    const int*   rc         = (const int*)d_in[3];
    const int*   tc         = (const int*)d_in[4];
    const int*   l2         = (const int*)d_in[5];
    const int*   l1         = (const int*)d_in[6];
    const int*   l0         = (const int*)d_in[7];
    const float* comp_table = (const float*)d_in[8];
    const float* op_table   = (const float*)d_in[9];
    const float* W1b        = (const float*)d_in[10];
    const float* b1b        = (const float*)d_in[11];
    const float* W2b        = (const float*)d_in[12];
    const float* b2b        = (const float*)d_in[13];
    const float* W1t        = (const float*)d_in[14];
    const float* b1t        = (const float*)d_in[15];
    const float* W2t        = (const float*)d_in[16];
    const float* b2t        = (const float*)d_in[17];
    const float* gma        = (const float*)d_in[18];
    const float* bta        = (const float*)d_in[19];

    int n_nodes = in_sizes[0];
    int n2 = in_sizes[5], n1 = in_sizes[6], n0 = in_sizes[7];

    cudaFuncSetAttribute(gemm1_kernel, cudaFuncAttributeMaxDynamicSharedMemorySize, G1_SMEM);
    cudaFuncSetAttribute(gemm2_kernel, cudaFuncAttributeMaxDynamicSharedMemorySize, G2_SMEM);

    __nv_bfloat16 *w1bh, *w1bl, *w1th, *w1tl, *w2bh, *w2bl, *w2th, *w2tl;
    cudaGetSymbolAddress((void**)&w1bh, g_W1bTh);
    cudaGetSymbolAddress((void**)&w1bl, g_W1bTl);
    cudaGetSymbolAddress((void**)&w1th, g_W1tTh);
    cudaGetSymbolAddress((void**)&w1tl, g_W1tTl);
    cudaGetSymbolAddress((void**)&w2bh, g_W2bTh);
    cudaGetSymbolAddress((void**)&w2bl, g_W2bTl);
    cudaGetSymbolAddress((void**)&w2th, g_W2tTh);
    cudaGetSymbolAddress((void**)&w2tl, g_W2tTl);

    dim3 tb(32, 8);
    convall_kernel<<<1152, tb>>>(W1b, W1t, W2b, W2t);
    init_all_kernel<<<n_nodes + 16, D>>>(comp_ids, comp_table, op_table, n_nodes);
    int tot = n2 + n1 + n0;
    compact_kernel<<<(tot + 255) / 256, 256>>>(l2, n2, l1, n1, l0, n0, tc);

    int ns[3] = {n2, n1, n0};
    const int* lidx[3] = {l2, l1, l0};
    for (int lvl = 0; lvl < 3; lvl++) {
        int nb1 = (ns[lvl] + MR1 - 1) / MR1;
        int nb2 = (ns[lvl] + MR2 - 1) / MR2;
        float* fout = (lvl == 2) ? (float*)d_out : nullptr;
        gemm1_kernel<<<nb1 * 4, NT1, G1_SMEM>>>(
            lvl, lidx[lvl], lc, rc, tc, op_ids,
            w1bh, w1bl, w1th, w1tl, b1b, b1t);
        gemm2_kernel<<<nb2 * 2, NT2, G2_SMEM>>>(
            lvl, lidx[lvl], lc, rc, tc,
            w2bh, w2bl, w2th, w2tl, b2b, b2t, gma, bta, fout);
    }
}

// round 15
// speedup vs baseline: 1.3276x; 1.3276x over previous
#include <cuda_runtime.h>
#include <cuda_bf16.h>
#include <math.h>
#include <stdint.h>

#define D 256
#define HH 512
#define MR1 64           // gemm1 rows per CTA
#define NT1 256
#define MR2 64           // gemm2 rows per CTA
#define NT2 256
#define MAX_NODES 65536
#define MAX_LVL 16384

// ---------------- device scratch ----------------
__device__ float g_embeds[MAX_NODES * D];
__device__ __nv_bfloat16 g_embh[MAX_NODES * D];
__device__ __nv_bfloat16 g_embl[MAX_NODES * D];
__device__ __nv_bfloat16 g_oph[16 * D], g_opl[16 * D];
__device__ int   g_list[6][MAX_LVL];
__device__ int   g_cnt[6];
__device__ __nv_bfloat16 g_W1bTh[HH * 768],  g_W1bTl[HH * 768];
__device__ __nv_bfloat16 g_W1tTh[HH * 1024], g_W1tTl[HH * 1024];
__device__ __nv_bfloat16 g_W2bTh[D * HH],    g_W2bTl[D * HH];
__device__ __nv_bfloat16 g_W2tTh[D * HH],    g_W2tTl[D * HH];
__device__ __nv_bfloat16 g_hh[2 * MAX_LVL * HH];
__device__ __nv_bfloat16 g_hl[2 * MAX_LVL * HH];

// ---------------- helpers ----------------
__device__ __forceinline__ uint32_t bfpack(float a, float b) {
    __nv_bfloat162 t = __floats2bfloat162_rn(a, b);
    return *reinterpret_cast<uint32_t*>(&t);
}
__device__ __forceinline__ float bfres(float a) {
    return a - __bfloat162float(__float2bfloat16_rn(a));
}
__device__ __forceinline__ float gelu_exact(float x) {
    return 0.5f * x * (1.0f + erff(x * 0.70710678118654752440f));
}
__device__ __forceinline__ void ldsm4(uint32_t r[4], uint32_t addr) {
    asm volatile("ldmatrix.sync.aligned.m8n8.x4.shared.b16 {%0,%1,%2,%3}, [%4];"
                 : "=r"(r[0]), "=r"(r[1]), "=r"(r[2]), "=r"(r[3]) : "r"(addr));
}
__device__ __forceinline__ void mma16816(float c[4], const uint32_t a[4],
                                         uint32_t b0, uint32_t b1) {
    asm volatile(
        "mma.sync.aligned.m16n8k16.row.col.f32.bf16.bf16.f32 "
        "{%0,%1,%2,%3}, {%4,%5,%6,%7}, {%8,%9}, {%0,%1,%2,%3};"
        : "+f"(c[0]), "+f"(c[1]), "+f"(c[2]), "+f"(c[3])
        : "r"(a[0]), "r"(a[1]), "r"(a[2]), "r"(a[3]), "r"(b0), "r"(b1));
}
__device__ __forceinline__ void cpasync16(uint32_t dst, const void* src) {
    asm volatile("cp.async.cg.shared.global [%0], [%1], 16;" :: "r"(dst), "l"(src));
}
#define CP_COMMIT() asm volatile("cp.async.commit_group;" ::: "memory")
#define CP_WAIT0()  asm volatile("cp.async.wait_group 0;" ::: "memory")

// ---------------- gemm1 smem layout (NT=256, M=64) ----------------
#define G1_PTRH 0
#define G1_PTRL 2048
#define G1_POOL 4096
#define G1_BUF  51200
#define G1_AH(b) (G1_POOL + (b) * G1_BUF)          // 64 x 80
#define G1_AL(b) (G1_AH(b) + 5120)
#define G1_BH(b) (G1_AH(b) + 10240)                // 256 x 80
#define G1_BL(b) (G1_AH(b) + 30720)
#define G1_SMEM (G1_POOL + 2 * G1_BUF)             // 106496 -> 2 CTAs/SM

// ---------------- gemm2 smem layout (NT=256, M=64) ----------------
#define G2_PTRF  0
#define G2_NODE  2048
#define G2_IDX   2304
#define G2_VALID 2560
#define G2_MU    2816
#define G2_RS    3072
#define G2_POOL  4096
#define G2_BUF   51200
#define G2_AH(b) (G2_POOL + (b) * G2_BUF)
#define G2_AL(b) (G2_AH(b) + 5120)
#define G2_BH(b) (G2_AH(b) + 10240)
#define G2_BL(b) (G2_AH(b) + 30720)
#define G2_PZ    G2_POOL
#define G2_SMEM (G2_POOL + 2 * G2_BUF)             // 106496

// ---------------- pre-kernels ----------------
__global__ void convall_kernel(const float* __restrict__ W1b, const float* __restrict__ W1t,
                               const float* __restrict__ W2b, const float* __restrict__ W2t) {
    __shared__ float tile[32][33];
    int bx = blockIdx.x;
    if (bx == 0 && threadIdx.y == 0 && threadIdx.x < 6) g_cnt[threadIdx.x] = 0;
    const float* in;
    __nv_bfloat16 *oh, *ol;
    int K, C, local;
    if (bx < 384)        { in = W1b; oh = g_W1bTh; ol = g_W1bTl; K = 768;  C = 512; local = bx; }
    else if (bx < 896)   { in = W1t; oh = g_W1tTh; ol = g_W1tTl; K = 1024; C = 512; local = bx - 384; }
    else if (bx < 1024)  { in = W2b; oh = g_W2bTh; ol = g_W2bTl; K = 512;  C = 256; local = bx - 896; }
    else                 { in = W2t; oh = g_W2tTh; ol = g_W2tTl; K = 512;  C = 256; local = bx - 1024; }
    int ktiles = K >> 5;
    int kt = local % ktiles, ct = local / ktiles;
    int k0 = kt * 32, c0 = ct * 32;
    int tx = threadIdx.x, ty = threadIdx.y;
    #pragma unroll
    for (int r = 0; r < 32; r += 8)
        tile[ty + r][tx] = in[(size_t)(k0 + ty + r) * C + c0 + tx];
    __syncthreads();
    #pragma unroll
    for (int r = 0; r < 32; r += 8) {
        float f = tile[tx][ty + r];
        __nv_bfloat16 h = __float2bfloat16_rn(f);
        float fl = f - __bfloat162float(h);
        size_t o = (size_t)(c0 + ty + r) * K + k0 + tx;
        oh[o] = h;
        ol[o] = __float2bfloat16_rn(fl);
    }
}

__global__ void init_all_kernel(const int* __restrict__ comp_ids,
                                const float* __restrict__ comp_table,
                                const float* __restrict__ op_table, int n_nodes) {
    int b = blockIdx.x, c = threadIdx.x;
    if (b < n_nodes) {
        float f = comp_table[comp_ids[b] * D + c];
        __nv_bfloat16 h = __float2bfloat16_rn(f);
        g_embeds[b * D + c] = f;
        g_embh[b * D + c] = h;
        g_embl[b * D + c] = __float2bfloat16_rn(f - __bfloat162float(h));
    } else {
        int row = b - n_nodes;
        float f = op_table[row * D + c];
        __nv_bfloat16 h = __float2bfloat16_rn(f);
        g_oph[row * D + c] = h;
        g_opl[row * D + c] = __float2bfloat16_rn(f - __bfloat162float(h));
    }
}

__global__ void compact_kernel(const int* __restrict__ lvl2, int n2,
                               const int* __restrict__ lvl1, int n1,
                               const int* __restrict__ lvl0, int n0,
                               const int* __restrict__ third) {
    int i = blockIdx.x * blockDim.x + threadIdx.x;
    int lvl, j;
    const int* idx;
    if (i < n2)                { lvl = 0; j = i;            idx = lvl2; }
    else if (i < n2 + n1)      { lvl = 1; j = i - n2;       idx = lvl1; }
    else if (i < n2 + n1 + n0) { lvl = 2; j = i - n2 - n1;  idx = lvl0; }
    else return;
    int node = idx[j];
    bool tern = (third[node] >= 0);
    int slot = lvl * 2 + (tern ? 0 : 1);
    int pos = atomicAdd(&g_cnt[slot], 1);
    g_list[slot][pos] = j;
}

// ---------------- GEMM1: h = gelu(x @ W1 + b1) -> global hi/lo ----------------
// grid: nb64 * 4 (bit0 = nsplit, bit1 = slotbit, rest = tile); NT=256, M=64
__global__ __launch_bounds__(NT1, 2)
void gemm1_kernel(int lvl,
                  const int* __restrict__ lvl_idx,
                  const int* __restrict__ lc, const int* __restrict__ rc,
                  const int* __restrict__ tcld,
                  const int* __restrict__ opids,
                  const __nv_bfloat16* __restrict__ W1bTh, const __nv_bfloat16* __restrict__ W1bTl,
                  const __nv_bfloat16* __restrict__ W1tTh, const __nv_bfloat16* __restrict__ W1tTl,
                  const float* __restrict__ b1b, const float* __restrict__ b1t) {
    extern __shared__ char smem[];
    int bx = blockIdx.x;
    int nsplit = bx & 1;
    int tern = ((bx >> 1) & 1) ? 0 : 1;
    int tile = bx >> 2;
    int slot = lvl * 2 + (tern ? 0 : 1);
    int cnt = g_cnt[slot];
    int base = tile * MR1;
    if (base >= cnt) return;

    const int K1 = tern ? 1024 : 768;
    const __nv_bfloat16* WTh = tern ? W1tTh : W1bTh;
    const __nv_bfloat16* WTl = tern ? W1tTl : W1bTl;
    const float* b1 = tern ? b1t : b1b;
    size_t hoff = (size_t)(tern ? 0 : MAX_LVL);

    int t = threadIdx.x;
    int lane = t & 31, wid = t >> 5;
    uint32_t sb = (uint32_t)__cvta_generic_to_shared(smem);

    uint64_t* sm_ptrh = (uint64_t*)(smem + G1_PTRH);
    uint64_t* sm_ptrl = (uint64_t*)(smem + G1_PTRL);

    const int* rows = g_list[slot];
    if (t < MR1) {
        int rr = min(base + t, cnt - 1);
        int i = rows[rr];
        int node = lvl_idx[i];
        size_t oo = (size_t)opids[node] * D;
        size_t lo_ = (size_t)lc[node] * D;
        size_t ro_ = (size_t)rc[node] * D;
        size_t to_ = tern ? (size_t)tcld[node] * D : lo_;
        sm_ptrh[t * 4 + 0] = (uint64_t)(g_oph + oo);
        sm_ptrh[t * 4 + 1] = (uint64_t)(g_embh + lo_);
        sm_ptrh[t * 4 + 2] = (uint64_t)(g_embh + ro_);
        sm_ptrh[t * 4 + 3] = (uint64_t)(g_embh + to_);
        sm_ptrl[t * 4 + 0] = (uint64_t)(g_opl + oo);
        sm_ptrl[t * 4 + 1] = (uint64_t)(g_embl + lo_);
        sm_ptrl[t * 4 + 2] = (uint64_t)(g_embl + ro_);
        sm_ptrl[t * 4 + 3] = (uint64_t)(g_embl + to_);
    }
    __syncthreads();

    int wm = wid & 1, wn = wid >> 1;       // 2 m-warps x 4 n-warps
    int m0 = wm * 32;
    int laneA_row  = lane & 15;
    int laneA_koff = (lane >> 4) * 16;
    int laneB_nrow = (lane & 7) + ((lane & 16) >> 1);
    int laneB_koff = ((lane >> 3) & 1) * 16;

    int a_row = t >> 2, a_q = t & 3;       // A: 64 rows x 16B per plane

    float c1[2][8][4];
    #pragma unroll
    for (int i = 0; i < 2; i++)
        #pragma unroll
        for (int j = 0; j < 8; j++)
            #pragma unroll
            for (int r = 0; r < 4; r++) c1[i][j][r] = 0.0f;

    int nkc = K1 >> 5;

    // prologue chunk 0: A (64 rows, 16B/thread/plane), B (256 rows, 64B/thread/plane)
    {
        const char* srcH = (const char*)sm_ptrh[a_row * 4 + 0] + a_q * 16;
        const char* srcL = (const char*)sm_ptrl[a_row * 4 + 0] + a_q * 16;
        cpasync16(sb + G1_AH(0) + a_row * 80 + a_q * 16, srcH);
        cpasync16(sb + G1_AL(0) + a_row * 80 + a_q * 16, srcL);
        const char* wsH = (const char*)(WTh + (size_t)(nsplit * 256 + t) * K1);
        const char* wsL = (const char*)(WTl + (size_t)(nsplit * 256 + t) * K1);
        uint32_t eH = sb + G1_BH(0) + t * 80;
        uint32_t eL = sb + G1_BL(0) + t * 80;
        #pragma unroll
        for (int j = 0; j < 4; j++) cpasync16(eH + j * 16, wsH + j * 16);
        #pragma unroll
        for (int j = 0; j < 4; j++) cpasync16(eL + j * 16, wsL + j * 16);
        CP_COMMIT();
    }
    for (int kc = 0; kc < nkc; kc++) {
        CP_WAIT0();
        __syncthreads();
        if (kc + 1 < nkc) {
            int buf = (kc + 1) & 1;
            int k0 = (kc + 1) * 32, seg = k0 >> 8;
            int sob = (k0 & 255) * 2 + a_q * 16;
            const char* srcH = (const char*)sm_ptrh[a_row * 4 + seg] + sob;
            const char* srcL = (const char*)sm_ptrl[a_row * 4 + seg] + sob;
            cpasync16(sb + G1_AH(buf) + a_row * 80 + a_q * 16, srcH);
            cpasync16(sb + G1_AL(buf) + a_row * 80 + a_q * 16, srcL);
            const char* wsH = (const char*)(WTh + (size_t)(nsplit * 256 + t) * K1 + k0);
            const char* wsL = (const char*)(WTl + (size_t)(nsplit * 256 + t) * K1 + k0);
            uint32_t eH = sb + G1_BH(buf) + t * 80;
            uint32_t eL = sb + G1_BL(buf) + t * 80;
            #pragma unroll
            for (int j = 0; j < 4; j++) cpasync16(eH + j * 16, wsH + j * 16);
            #pragma unroll
            for (int j = 0; j < 4; j++) cpasync16(eL + j * 16, wsL + j * 16);
            CP_COMMIT();
        }
        int buf = kc & 1;
        uint32_t AHp = G1_AH(buf), ALp = G1_AL(buf), BHp = G1_BH(buf), BLp = G1_BL(buf);
        #pragma unroll
        for (int ks = 0; ks < 2; ks++) {
            int kb = ks * 32;
            uint32_t ah0[4], ah1[4], al0[4], al1[4];
            ldsm4(ah0, sb + AHp + (m0 + laneA_row) * 80 + kb + laneA_koff);
            ldsm4(ah1, sb + AHp + (m0 + 16 + laneA_row) * 80 + kb + laneA_koff);
            ldsm4(al0, sb + ALp + (m0 + laneA_row) * 80 + kb + laneA_koff);
            ldsm4(al1, sb + ALp + (m0 + 16 + laneA_row) * 80 + kb + laneA_koff);
            #pragma unroll
            for (int g = 0; g < 2; g++) {
                int ng = wn * 64 + g * 32;
                int jb = g * 4;
                uint32_t bh0[4], bh1[4], bl0[4], bl1[4];
                ldsm4(bh0, sb + BHp + (ng + laneB_nrow) * 80 + kb + laneB_koff);
                ldsm4(bh1, sb + BHp + (ng + 16 + laneB_nrow) * 80 + kb + laneB_koff);
                mma16816(c1[0][jb + 0], ah0, bh0[0], bh0[1]);
                mma16816(c1[0][jb + 1], ah0, bh0[2], bh0[3]);
                mma16816(c1[0][jb + 2], ah0, bh1[0], bh1[1]);
                mma16816(c1[0][jb + 3], ah0, bh1[2], bh1[3]);
                mma16816(c1[1][jb + 0], ah1, bh0[0], bh0[1]);
                mma16816(c1[1][jb + 1], ah1, bh0[2], bh0[3]);
                mma16816(c1[1][jb + 2], ah1, bh1[0], bh1[1]);
                mma16816(c1[1][jb + 3], ah1, bh1[2], bh1[3]);
                ldsm4(bl0, sb + BLp + (ng + laneB_nrow) * 80 + kb + laneB_koff);
                ldsm4(bl1, sb + BLp + (ng + 16 + laneB_nrow) * 80 + kb + laneB_koff);
                mma16816(c1[0][jb + 0], ah0, bl0[0], bl0[1]);
                mma16816(c1[0][jb + 1], ah0, bl0[2], bl0[3]);
                mma16816(c1[0][jb + 2], ah0, bl1[0], bl1[1]);
                mma16816(c1[0][jb + 3], ah0, bl1[2], bl1[3]);
                mma16816(c1[1][jb + 0], ah1, bl0[0], bl0[1]);
                mma16816(c1[1][jb + 1], ah1, bl0[2], bl0[3]);
                mma16816(c1[1][jb + 2], ah1, bl1[0], bl1[1]);
                mma16816(c1[1][jb + 3], ah1, bl1[2], bl1[3]);
                mma16816(c1[0][jb + 0], al0, bh0[0], bh0[1]);
                mma16816(c1[0][jb + 1], al0, bh0[2], bh0[3]);
                mma16816(c1[0][jb + 2], al0, bh1[0], bh1[1]);
                mma16816(c1[0][jb + 3], al0, bh1[2], bh1[3]);
                mma16816(c1[1][jb + 0], al1, bh0[0], bh0[1]);
                mma16816(c1[1][jb + 1], al1, bh0[2], bh0[3]);
                mma16816(c1[1][jb + 2], al1, bh1[0], bh1[1]);
                mma16816(c1[1][jb + 3], al1, bh1[2], bh1[3]);
            }
        }
    }

    // epilogue: bias + gelu -> global h hi/lo
    {
        #pragma unroll
        for (int j = 0; j < 8; j++) {
            int ncol = wn * 64 + j * 8 + (lane & 3) * 2;
            int gcol = nsplit * 256 + ncol;
            float2 bb = *(const float2*)(b1 + gcol);
            #pragma unroll
            for (int i = 0; i < 2; i++) {
                int r0 = m0 + i * 16 + (lane >> 2);
                size_t gr0 = (hoff + base + r0) * HH + gcol;
                size_t gr1 = (hoff + base + r0 + 8) * HH + gcol;
                float h0 = gelu_exact(c1[i][j][0] + bb.x);
                float h1 = gelu_exact(c1[i][j][1] + bb.y);
                *(uint32_t*)(g_hh + gr0) = bfpack(h0, h1);
                *(uint32_t*)(g_hl + gr0) = bfpack(bfres(h0), bfres(h1));
                float h2 = gelu_exact(c1[i][j][2] + bb.x);
                float h3 = gelu_exact(c1[i][j][3] + bb.y);
                *(uint32_t*)(g_hh + gr1) = bfpack(h2, h3);
                *(uint32_t*)(g_hl + gr1) = bfpack(bfres(h2), bfres(h3));
            }
        }
    }
}

// ---------------- GEMM2: y = h @ W2 + b2; residual + LN ----------------
__global__ __launch_bounds__(NT2, 2)
void gemm2_kernel(int lvl,
                  const int* __restrict__ lvl_idx,
                  const int* __restrict__ lc, const int* __restrict__ rc,
                  const int* __restrict__ tcld,
                  const __nv_bfloat16* __restrict__ W2bTh, const __nv_bfloat16* __restrict__ W2bTl,
                  const __nv_bfloat16* __restrict__ W2tTh, const __nv_bfloat16* __restrict__ W2tTl,
                  const float* __restrict__ b2b, const float* __restrict__ b2t,
                  const float* __restrict__ gma, const float* __restrict__ bta,
                  float* __restrict__ final_out) {
    extern __shared__ char smem[];
    int bx = blockIdx.x;
    int tern = (bx & 1) ? 0 : 1;
    int tile = bx >> 1;
    int slot = lvl * 2 + (tern ? 0 : 1);
    int cnt = g_cnt[slot];
    int base = tile * MR2;
    if (base >= cnt) return;

    const __nv_bfloat16* WTh = tern ? W2tTh : W2bTh;
    const __nv_bfloat16* WTl = tern ? W2tTl : W2bTl;
    const float* b2 = tern ? b2t : b2b;
    size_t hoff = (size_t)(tern ? 0 : MAX_LVL);

    int t = threadIdx.x;
    int lane = t & 31, wid = t >> 5;
    uint32_t sb = (uint32_t)__cvta_generic_to_shared(smem);

    uint64_t* sm_ptrf = (uint64_t*)(smem + G2_PTRF);
    int* sm_node  = (int*)(smem + G2_NODE);
    int* sm_idx   = (int*)(smem + G2_IDX);
    int* sm_valid = (int*)(smem + G2_VALID);
    float* sm_mu  = (float*)(smem + G2_MU);
    float* sm_rs  = (float*)(smem + G2_RS);

    const int* rows = g_list[slot];
    if (t < MR2) {
        int rr = min(base + t, cnt - 1);
        int i = rows[rr];
        int node = lvl_idx[i];
        sm_node[t] = node;
        sm_idx[t] = i;
        sm_valid[t] = (base + t < cnt) ? 1 : 0;
        size_t lo_ = (size_t)lc[node] * D;
        size_t ro_ = (size_t)rc[node] * D;
        size_t to_ = tern ? (size_t)tcld[node] * D : lo_;
        sm_ptrf[t * 4 + 1] = (uint64_t)(g_embeds + lo_);
        sm_ptrf[t * 4 + 2] = (uint64_t)(g_embeds + ro_);
        sm_ptrf[t * 4 + 3] = (uint64_t)(g_embeds + to_);
    }
    __syncthreads();

    int wm = wid & 1, wn = wid >> 1;
    int m0 = wm * 32;
    int laneA_row  = lane & 15;
    int laneA_koff = (lane >> 4) * 16;
    int laneB_nrow = (lane & 7) + ((lane & 16) >> 1);
    int laneB_koff = ((lane >> 3) & 1) * 16;

    int a_row = t >> 2, a_q = t & 3;

    float c2[2][8][4];
    #pragma unroll
    for (int i = 0; i < 2; i++)
        #pragma unroll
        for (int j = 0; j < 8; j++)
            #pragma unroll
            for (int r = 0; r < 4; r++) c2[i][j][r] = 0.0f;

    // prologue chunk 0
    {
        const char* srcH = (const char*)(g_hh + (hoff + base + a_row) * HH) + a_q * 16;
        const char* srcL = (const char*)(g_hl + (hoff + base + a_row) * HH) + a_q * 16;
        cpasync16(sb + G2_AH(0) + a_row * 80 + a_q * 16, srcH);
        cpasync16(sb + G2_AL(0) + a_row * 80 + a_q * 16, srcL);
        const char* wsH = (const char*)(WTh + (size_t)t * HH);
        const char* wsL = (const char*)(WTl + (size_t)t * HH);
        uint32_t eH = sb + G2_BH(0) + t * 80;
        uint32_t eL = sb + G2_BL(0) + t * 80;
        #pragma unroll
        for (int j = 0; j < 4; j++) cpasync16(eH + j * 16, wsH + j * 16);
        #pragma unroll
        for (int j = 0; j < 4; j++) cpasync16(eL + j * 16, wsL + j * 16);
        CP_COMMIT();
    }
    for (int kc = 0; kc < 16; kc++) {
        CP_WAIT0();
        __syncthreads();
        if (kc + 1 < 16) {
            int buf = (kc + 1) & 1;
            int k0 = (kc + 1) * 32;
            const char* srcH = (const char*)(g_hh + (hoff + base + a_row) * HH + k0) + a_q * 16;
            const char* srcL = (const char*)(g_hl + (hoff + base + a_row) * HH + k0) + a_q * 16;
            cpasync16(sb + G2_AH(buf) + a_row * 80 + a_q * 16, srcH);
            cpasync16(sb + G2_AL(buf) + a_row * 80 + a_q * 16, srcL);
            const char* wsH = (const char*)(WTh + (size_t)t * HH + k0);
            const char* wsL = (const char*)(WTl + (size_t)t * HH + k0);
            uint32_t eH = sb + G2_BH(buf) + t * 80;
            uint32_t eL = sb + G2_BL(buf) + t * 80;
            #pragma unroll
            for (int j = 0; j < 4; j++) cpasync16(eH + j * 16, wsH + j * 16);
            #pragma unroll
            for (int j = 0; j < 4; j++) cpasync16(eL + j * 16, wsL + j * 16);
            CP_COMMIT();
        }
        int buf = kc & 1;
        uint32_t AHp = G2_AH(buf), ALp = G2_AL(buf), BHp = G2_BH(buf), BLp = G2_BL(buf);
        #pragma unroll
        for (int ks = 0; ks < 2; ks++) {
            int kb = ks * 32;
            uint32_t ah0[4], ah1[4], al0[4], al1[4];
            ldsm4(ah0, sb + AHp + (m0 + laneA_row) * 80 + kb + laneA_koff);
            ldsm4(ah1, sb + AHp + (m0 + 16 + laneA_row) * 80 + kb + laneA_koff);
            ldsm4(al0, sb + ALp + (m0 + laneA_row) * 80 + kb + laneA_koff);
            ldsm4(al1, sb + ALp + (m0 + 16 + laneA_row) * 80 + kb + laneA_koff);
            #pragma unroll
            for (int g = 0; g < 2; g++) {
                int ng = wn * 64 + g * 32;
                int jb = g * 4;
                uint32_t bh0[4], bh1[4], bl0[4], bl1[4];
                ldsm4(bh0, sb + BHp + (ng + laneB_nrow) * 80 + kb + laneB_koff);
                ldsm4(bh1, sb + BHp + (ng + 16 + laneB_nrow) * 80 + kb + laneB_koff);
                mma16816(c2[0][jb + 0], ah0, bh0[0], bh0[1]);
                mma16816(c2[0][jb + 1], ah0, bh0[2], bh0[3]);
                mma16816(c2[0][jb + 2], ah0, bh1[0], bh1[1]);
                mma16816(c2[0][jb + 3], ah0, bh1[2], bh1[3]);
                mma16816(c2[1][jb + 0], ah1, bh0[0], bh0[1]);
                mma16816(c2[1][jb + 1], ah1, bh0[2], bh0[3]);
                mma16816(c2[1][jb + 2], ah1, bh1[0], bh1[1]);
                mma16816(c2[1][jb + 3], ah1, bh1[2], bh1[3]);
                ldsm4(bl0, sb + BLp + (ng + laneB_nrow) * 80 + kb + laneB_koff);
                ldsm4(bl1, sb + BLp + (ng + 16 + laneB_nrow) * 80 + kb + laneB_koff);
                mma16816(c2[0][jb + 0], ah0, bl0[0], bl0[1]);
                mma16816(c2[0][jb + 1], ah0, bl0[2], bl0[3]);
                mma16816(c2[0][jb + 2], ah0, bl1[0], bl1[1]);
                mma16816(c2[0][jb + 3], ah0, bl1[2], bl1[3]);
                mma16816(c2[1][jb + 0], ah1, bl0[0], bl0[1]);
                mma16816(c2[1][jb + 1], ah1, bl0[2], bl0[3]);
                mma16816(c2[1][jb + 2], ah1, bl1[0], bl1[1]);
                mma16816(c2[1][jb + 3], ah1, bl1[2], bl1[3]);
                mma16816(c2[0][jb + 0], al0, bh0[0], bh0[1]);
                mma16816(c2[0][jb + 1], al0, bh0[2], bh0[3]);
                mma16816(c2[0][jb + 2], al0, bh1[0], bh1[1]);
                mma16816(c2[0][jb + 3], al0, bh1[2], bh1[3]);
                mma16816(c2[1][jb + 0], al1, bh0[0], bh0[1]);
                mma16816(c2[1][jb + 1], al1, bh0[2], bh0[3]);
                mma16816(c2[1][jb + 2], al1, bh1[0], bh1[1]);
                mma16816(c2[1][jb + 3], al1, bh1[2], bh1[3]);
            }
        }
    }
    __syncthreads();

    // epilogue: bias + residual -> zbuf
    {
        #pragma unroll
        for (int i = 0; i < 2; i++) {
            #pragma unroll
            for (int rh = 0; rh < 2; rh++) {
                int m = m0 + i * 16 + rh * 8 + (lane >> 2);
                const float* lp = (const float*)sm_ptrf[m * 4 + 1];
                const float* rp = (const float*)sm_ptrf[m * 4 + 2];
                const float* tp = (const float*)sm_ptrf[m * 4 + 3];
                #pragma unroll
                for (int j = 0; j < 8; j++) {
                    int n = wn * 64 + j * 8 + (lane & 3) * 2;
                    float2 bv = *(const float2*)(b2 + n);
                    float y0 = c2[i][j][rh * 2]     + bv.x;
                    float y1 = c2[i][j][rh * 2 + 1] + bv.y;
                    float2 lv = *(const float2*)(lp + n);
                    float2 rv = *(const float2*)(rp + n);
                    if (tern) {
                        float2 tv = *(const float2*)(tp + n);
                        y0 += (lv.x + rv.x + tv.x) * (1.0f / 3.0f);
                        y1 += (lv.y + rv.y + tv.y) * (1.0f / 3.0f);
                    } else {
                        y0 += lv.x + rv.x;
                        y1 += lv.y + rv.y;
                    }
                    *(float2*)(smem + G2_PZ + m * 1040 + n * 4) = make_float2(y0, y1);
                }
            }
        }
    }
    __syncthreads();

    if (t < MR2) {
        const float* zr = (const float*)(smem + G2_PZ + t * 1040);
        float s = 0.0f, s2 = 0.0f;
        #pragma unroll 8
        for (int c = 0; c < D; c++) {
            float v = zr[c];
            s += v;
            s2 += v * v;
        }
        float mu = s * (1.0f / 256.0f);
        float var = s2 * (1.0f / 256.0f) - mu * mu;
        sm_mu[t] = mu;
        sm_rs[t] = rsqrtf(var + 1e-5f);
    }
    __syncthreads();

    for (int idx = t; idx < MR2 * 64; idx += NT2) {
        int row = idx >> 6, q = idx & 63;
        if (!sm_valid[row]) continue;
        float mu = sm_mu[row], rs = sm_rs[row];
        const float* zr = (const float*)(smem + G2_PZ + row * 1040) + q * 4;
        float4 g4 = *(const float4*)(gma + q * 4);
        float4 be = *(const float4*)(bta + q * 4);
        float4 o;
        o.x = (zr[0] - mu) * rs * g4.x + be.x;
        o.y = (zr[1] - mu) * rs * g4.y + be.y;
        o.z = (zr[2] - mu) * rs * g4.z + be.z;
        o.w = (zr[3] - mu) * rs * g4.w + be.w;
        if (final_out) {
            *(float4*)(final_out + (size_t)sm_idx[row] * D + q * 4) = o;
        } else {
            size_t off = (size_t)sm_node[row] * D + q * 4;
            *(float4*)(g_embeds + off) = o;
            uint2 hv, lv;
            hv.x = bfpack(o.x, o.y);
            hv.y = bfpack(o.z, o.w);
            lv.x = bfpack(bfres(o.x), bfres(o.y));
            lv.y = bfpack(bfres(o.z), bfres(o.w));
            *(uint2*)(g_embh + off) = hv;
            *(uint2*)(g_embl + off) = lv;
        }
    }
}

// ---------------- launcher ----------------
extern "C" void kernel_launch(void* const* d_in, const int* in_sizes, int n_in,
                              void* d_out, int out_size) {
    const int*   comp_ids   = (const int*)d_in[0];
    const int*   op_ids     = (const int*)d_in[1];
    const int*   lc         = (const int*)d_in[2];
    const int*   rc         = (const int*)d_in[3];
    const int*   tc         = (const int*)d_in[4];
    const int*   l2         = (const int*)d_in[5];
    const int*   l1         = (const int*)d_in[6];
    const int*   l0         = (const int*)d_in[7];
    const float* comp_table = (const float*)d_in[8];
    const float* op_table   = (const float*)d_in[9];
    const float* W1b        = (const float*)d_in[10];
    const float* b1b        = (const float*)d_in[11];
    const float* W2b        = (const float*)d_in[12];
    const float* b2b        = (const float*)d_in[13];
    const float* W1t        = (const float*)d_in[14];
    const float* b1t        = (const float*)d_in[15];
    const float* W2t        = (const float*)d_in[16];
    const float* b2t        = (const float*)d_in[17];
    const float* gma        = (const float*)d_in[18];
    const float* bta        = (const float*)d_in[19];

    int n_nodes = in_sizes[0];
    int n2 = in_sizes[5], n1 = in_sizes[6], n0 = in_sizes[7];

    cudaFuncSetAttribute(gemm1_kernel, cudaFuncAttributeMaxDynamicSharedMemorySize, G1_SMEM);
    cudaFuncSetAttribute(gemm2_kernel, cudaFuncAttributeMaxDynamicSharedMemorySize, G2_SMEM);

    __nv_bfloat16 *w1bh, *w1bl, *w1th, *w1tl, *w2bh, *w2bl, *w2th, *w2tl;
    cudaGetSymbolAddress((void**)&w1bh, g_W1bTh);
    cudaGetSymbolAddress((void**)&w1bl, g_W1bTl);
    cudaGetSymbolAddress((void**)&w1th, g_W1tTh);
    cudaGetSymbolAddress((void**)&w1tl, g_W1tTl);
    cudaGetSymbolAddress((void**)&w2bh, g_W2bTh);
    cudaGetSymbolAddress((void**)&w2bl, g_W2bTl);
    cudaGetSymbolAddress((void**)&w2th, g_W2tTh);
    cudaGetSymbolAddress((void**)&w2tl, g_W2tTl);

    dim3 tb(32, 8);
    convall_kernel<<<1152, tb>>>(W1b, W1t, W2b, W2t);
    init_all_kernel<<<n_nodes + 16, D>>>(comp_ids, comp_table, op_table, n_nodes);
    int tot = n2 + n1 + n0;
    compact_kernel<<<(tot + 255) / 256, 256>>>(l2, n2, l1, n1, l0, n0, tc);

    int ns[3] = {n2, n1, n0};
    const int* lidx[3] = {l2, l1, l0};
    for (int lvl = 0; lvl < 3; lvl++) {
        int nb1 = (ns[lvl] + MR1 - 1) / MR1;
        int nb2 = (ns[lvl] + MR2 - 1) / MR2;
        float* fout = (lvl == 2) ? (float*)d_out : nullptr;
        gemm1_kernel<<<nb1 * 4, NT1, G1_SMEM>>>(
            lvl, lidx[lvl], lc, rc, tc, op_ids,
            w1bh, w1bl, w1th, w1tl, b1b, b1t);
        gemm2_kernel<<<nb2 * 2, NT2, G2_SMEM>>>(
            lvl, lidx[lvl], lc, rc, tc,
            w2bh, w2bl, w2th, w2tl, b2b, b2t, gma, bta, fout);
    }
}

// round 16
// speedup vs baseline: 1.5079x; 1.1358x over previous
#include <cuda_runtime.h>
#include <cuda_bf16.h>
#include <math.h>
#include <stdint.h>

#define D 256
#define HH 512
#define MR1 64           // gemm1 rows per CTA
#define NT1 256
#define MR2 64           // gemm2 rows per CTA
#define NT2 256
#define MAX_NODES 65536
#define MAX_LVL 16384

// ---------------- device scratch ----------------
__device__ float g_embeds[MAX_NODES * D];
__device__ __nv_bfloat16 g_embh[MAX_NODES * D];
__device__ __nv_bfloat16 g_embl[MAX_NODES * D];
__device__ __nv_bfloat16 g_oph[16 * D], g_opl[16 * D];
__device__ int   g_list[6][MAX_LVL];
__device__ int   g_cnt[6];
__device__ __nv_bfloat16 g_W1bTh[HH * 768],  g_W1bTl[HH * 768];
__device__ __nv_bfloat16 g_W1tTh[HH * 1024], g_W1tTl[HH * 1024];
__device__ __nv_bfloat16 g_W2bTh[D * HH],    g_W2bTl[D * HH];
__device__ __nv_bfloat16 g_W2tTh[D * HH],    g_W2tTl[D * HH];
__device__ __nv_bfloat16 g_hh[2 * MAX_LVL * HH];
__device__ __nv_bfloat16 g_hl[2 * MAX_LVL * HH];

// ---------------- helpers ----------------
__device__ __forceinline__ uint32_t bfpack(float a, float b) {
    __nv_bfloat162 t = __floats2bfloat162_rn(a, b);
    return *reinterpret_cast<uint32_t*>(&t);
}
__device__ __forceinline__ float bfres(float a) {
    return a - __bfloat162float(__float2bfloat16_rn(a));
}
__device__ __forceinline__ float gelu_exact(float x) {
    return 0.5f * x * (1.0f + erff(x * 0.70710678118654752440f));
}
__device__ __forceinline__ void ldsm4(uint32_t r[4], uint32_t addr) {
    asm volatile("ldmatrix.sync.aligned.m8n8.x4.shared.b16 {%0,%1,%2,%3}, [%4];"
                 : "=r"(r[0]), "=r"(r[1]), "=r"(r[2]), "=r"(r[3]) : "r"(addr));
}
__device__ __forceinline__ void mma16816(float c[4], const uint32_t a[4],
                                         uint32_t b0, uint32_t b1) {
    asm volatile(
        "mma.sync.aligned.m16n8k16.row.col.f32.bf16.bf16.f32 "
        "{%0,%1,%2,%3}, {%4,%5,%6,%7}, {%8,%9}, {%0,%1,%2,%3};"
        : "+f"(c[0]), "+f"(c[1]), "+f"(c[2]), "+f"(c[3])
        : "r"(a[0]), "r"(a[1]), "r"(a[2]), "r"(a[3]), "r"(b0), "r"(b1));
}
__device__ __forceinline__ void cpasync16(uint32_t dst, const void* src) {
    asm volatile("cp.async.cg.shared.global [%0], [%1], 16;" :: "r"(dst), "l"(src));
}
#define CP_COMMIT() asm volatile("cp.async.commit_group;" ::: "memory")
#define CP_WAIT0()  asm volatile("cp.async.wait_group 0;" ::: "memory")

// ---------------- gemm1 smem layout (NT=256, M=64, N=128) ----------------
#define G1_PTRH 0
#define G1_PTRL 2048
#define G1_POOL 4096
#define G1_BUF  30720
#define G1_AH(b) (G1_POOL + (b) * G1_BUF)          // 64 x 80
#define G1_AL(b) (G1_AH(b) + 5120)
#define G1_BH(b) (G1_AH(b) + 10240)                // 128 x 80
#define G1_BL(b) (G1_AH(b) + 20480)
#define G1_SMEM (G1_POOL + 2 * G1_BUF)             // 65536 -> 3 CTAs/SM

// ---------------- gemm2 smem layout (NT=256, M=64) ----------------
#define G2_PTRF  0
#define G2_NODE  2048
#define G2_IDX   2304
#define G2_VALID 2560
#define G2_MU    2816
#define G2_RS    3072
#define G2_POOL  4096
#define G2_BUF   51200
#define G2_AH(b) (G2_POOL + (b) * G2_BUF)
#define G2_AL(b) (G2_AH(b) + 5120)
#define G2_BH(b) (G2_AH(b) + 10240)
#define G2_BL(b) (G2_AH(b) + 30720)
#define G2_PZ    G2_POOL
#define G2_SMEM (G2_POOL + 2 * G2_BUF)             // 106496

// ---------------- pre-kernels ----------------
__global__ void convall_kernel(const float* __restrict__ W1b, const float* __restrict__ W1t,
                               const float* __restrict__ W2b, const float* __restrict__ W2t) {
    __shared__ float tile[32][33];
    int bx = blockIdx.x;
    if (bx == 0 && threadIdx.y == 0 && threadIdx.x < 6) g_cnt[threadIdx.x] = 0;
    const float* in;
    __nv_bfloat16 *oh, *ol;
    int K, C, local;
    if (bx < 384)        { in = W1b; oh = g_W1bTh; ol = g_W1bTl; K = 768;  C = 512; local = bx; }
    else if (bx < 896)   { in = W1t; oh = g_W1tTh; ol = g_W1tTl; K = 1024; C = 512; local = bx - 384; }
    else if (bx < 1024)  { in = W2b; oh = g_W2bTh; ol = g_W2bTl; K = 512;  C = 256; local = bx - 896; }
    else                 { in = W2t; oh = g_W2tTh; ol = g_W2tTl; K = 512;  C = 256; local = bx - 1024; }
    int ktiles = K >> 5;
    int kt = local % ktiles, ct = local / ktiles;
    int k0 = kt * 32, c0 = ct * 32;
    int tx = threadIdx.x, ty = threadIdx.y;
    #pragma unroll
    for (int r = 0; r < 32; r += 8)
        tile[ty + r][tx] = in[(size_t)(k0 + ty + r) * C + c0 + tx];
    __syncthreads();
    #pragma unroll
    for (int r = 0; r < 32; r += 8) {
        float f = tile[tx][ty + r];
        __nv_bfloat16 h = __float2bfloat16_rn(f);
        float fl = f - __bfloat162float(h);
        size_t o = (size_t)(c0 + ty + r) * K + k0 + tx;
        oh[o] = h;
        ol[o] = __float2bfloat16_rn(fl);
    }
}

__global__ void init_all_kernel(const int* __restrict__ comp_ids,
                                const float* __restrict__ comp_table,
                                const float* __restrict__ op_table, int n_nodes) {
    int b = blockIdx.x, c = threadIdx.x;
    if (b < n_nodes) {
        float f = comp_table[comp_ids[b] * D + c];
        __nv_bfloat16 h = __float2bfloat16_rn(f);
        g_embeds[b * D + c] = f;
        g_embh[b * D + c] = h;
        g_embl[b * D + c] = __float2bfloat16_rn(f - __bfloat162float(h));
    } else {
        int row = b - n_nodes;
        float f = op_table[row * D + c];
        __nv_bfloat16 h = __float2bfloat16_rn(f);
        g_oph[row * D + c] = h;
        g_opl[row * D + c] = __float2bfloat16_rn(f - __bfloat162float(h));
    }
}

__global__ void compact_kernel(const int* __restrict__ lvl2, int n2,
                               const int* __restrict__ lvl1, int n1,
                               const int* __restrict__ lvl0, int n0,
                               const int* __restrict__ third) {
    int i = blockIdx.x * blockDim.x + threadIdx.x;
    int lvl, j;
    const int* idx;
    if (i < n2)                { lvl = 0; j = i;            idx = lvl2; }
    else if (i < n2 + n1)      { lvl = 1; j = i - n2;       idx = lvl1; }
    else if (i < n2 + n1 + n0) { lvl = 2; j = i - n2 - n1;  idx = lvl0; }
    else return;
    int node = idx[j];
    bool tern = (third[node] >= 0);
    int slot = lvl * 2 + (tern ? 0 : 1);
    int pos = atomicAdd(&g_cnt[slot], 1);
    g_list[slot][pos] = j;
}

// ---------------- GEMM1: h = gelu(x @ W1 + b1) -> global hi/lo ----------------
// grid: nb64 * 8 (bits0-1 = nsplit (of 4 x 128 cols), bit2 = slotbit, rest = tile)
__global__ __launch_bounds__(NT1, 3)
void gemm1_kernel(int lvl,
                  const int* __restrict__ lvl_idx,
                  const int* __restrict__ lc, const int* __restrict__ rc,
                  const int* __restrict__ tcld,
                  const int* __restrict__ opids,
                  const __nv_bfloat16* __restrict__ W1bTh, const __nv_bfloat16* __restrict__ W1bTl,
                  const __nv_bfloat16* __restrict__ W1tTh, const __nv_bfloat16* __restrict__ W1tTl,
                  const float* __restrict__ b1b, const float* __restrict__ b1t) {
    extern __shared__ char smem[];
    int bx = blockIdx.x;
    int nsplit = bx & 3;
    int tern = ((bx >> 2) & 1) ? 0 : 1;
    int tile = bx >> 3;
    int slot = lvl * 2 + (tern ? 0 : 1);
    int cnt = g_cnt[slot];
    int base = tile * MR1;
    if (base >= cnt) return;

    const int K1 = tern ? 1024 : 768;
    const __nv_bfloat16* WTh = tern ? W1tTh : W1bTh;
    const __nv_bfloat16* WTl = tern ? W1tTl : W1bTl;
    const float* b1 = tern ? b1t : b1b;
    size_t hoff = (size_t)(tern ? 0 : MAX_LVL);

    int t = threadIdx.x;
    int lane = t & 31, wid = t >> 5;
    uint32_t sb = (uint32_t)__cvta_generic_to_shared(smem);

    uint64_t* sm_ptrh = (uint64_t*)(smem + G1_PTRH);
    uint64_t* sm_ptrl = (uint64_t*)(smem + G1_PTRL);

    const int* rows = g_list[slot];
    if (t < MR1) {
        int rr = min(base + t, cnt - 1);
        int i = rows[rr];
        int node = lvl_idx[i];
        size_t oo = (size_t)opids[node] * D;
        size_t lo_ = (size_t)lc[node] * D;
        size_t ro_ = (size_t)rc[node] * D;
        size_t to_ = tern ? (size_t)tcld[node] * D : lo_;
        sm_ptrh[t * 4 + 0] = (uint64_t)(g_oph + oo);
        sm_ptrh[t * 4 + 1] = (uint64_t)(g_embh + lo_);
        sm_ptrh[t * 4 + 2] = (uint64_t)(g_embh + ro_);
        sm_ptrh[t * 4 + 3] = (uint64_t)(g_embh + to_);
        sm_ptrl[t * 4 + 0] = (uint64_t)(g_opl + oo);
        sm_ptrl[t * 4 + 1] = (uint64_t)(g_embl + lo_);
        sm_ptrl[t * 4 + 2] = (uint64_t)(g_embl + ro_);
        sm_ptrl[t * 4 + 3] = (uint64_t)(g_embl + to_);
    }
    __syncthreads();

    int wm = wid & 1, wn = wid >> 1;       // 2 m-warps x 4 n-warps (n32 each)
    int m0 = wm * 32;
    int laneA_row  = lane & 15;
    int laneA_koff = (lane >> 4) * 16;
    int laneB_nrow = (lane & 7) + ((lane & 16) >> 1);
    int laneB_koff = ((lane >> 3) & 1) * 16;

    int a_row = t >> 2, a_q = t & 3;       // A: 64 rows x 16B per plane
    int b_r = t >> 1, b_half = t & 1;      // B: 128 rows, 32B/thread per plane

    float c1[2][4][4];
    #pragma unroll
    for (int i = 0; i < 2; i++)
        #pragma unroll
        for (int j = 0; j < 4; j++)
            #pragma unroll
            for (int r = 0; r < 4; r++) c1[i][j][r] = 0.0f;

    int nkc = K1 >> 5;
    int wbase = nsplit * 128;

    // prologue chunk 0
    {
        const char* srcH = (const char*)sm_ptrh[a_row * 4 + 0] + a_q * 16;
        const char* srcL = (const char*)sm_ptrl[a_row * 4 + 0] + a_q * 16;
        cpasync16(sb + G1_AH(0) + a_row * 80 + a_q * 16, srcH);
        cpasync16(sb + G1_AL(0) + a_row * 80 + a_q * 16, srcL);
        const char* wsH = (const char*)(WTh + (size_t)(wbase + b_r) * K1 + b_half * 16);
        const char* wsL = (const char*)(WTl + (size_t)(wbase + b_r) * K1 + b_half * 16);
        uint32_t eH = sb + G1_BH(0) + b_r * 80 + b_half * 32;
        uint32_t eL = sb + G1_BL(0) + b_r * 80 + b_half * 32;
        cpasync16(eH, wsH); cpasync16(eH + 16, wsH + 16);
        cpasync16(eL, wsL); cpasync16(eL + 16, wsL + 16);
        CP_COMMIT();
    }
    for (int kc = 0; kc < nkc; kc++) {
        CP_WAIT0();
        __syncthreads();
        if (kc + 1 < nkc) {
            int buf = (kc + 1) & 1;
            int k0 = (kc + 1) * 32, seg = k0 >> 8;
            int sob = (k0 & 255) * 2 + a_q * 16;
            const char* srcH = (const char*)sm_ptrh[a_row * 4 + seg] + sob;
            const char* srcL = (const char*)sm_ptrl[a_row * 4 + seg] + sob;
            cpasync16(sb + G1_AH(buf) + a_row * 80 + a_q * 16, srcH);
            cpasync16(sb + G1_AL(buf) + a_row * 80 + a_q * 16, srcL);
            const char* wsH = (const char*)(WTh + (size_t)(wbase + b_r) * K1 + k0 + b_half * 16);
            const char* wsL = (const char*)(WTl + (size_t)(wbase + b_r) * K1 + k0 + b_half * 16);
            uint32_t eH = sb + G1_BH(buf) + b_r * 80 + b_half * 32;
            uint32_t eL = sb + G1_BL(buf) + b_r * 80 + b_half * 32;
            cpasync16(eH, wsH); cpasync16(eH + 16, wsH + 16);
            cpasync16(eL, wsL); cpasync16(eL + 16, wsL + 16);
            CP_COMMIT();
        }
        int buf = kc & 1;
        uint32_t AHp = G1_AH(buf), ALp = G1_AL(buf), BHp = G1_BH(buf), BLp = G1_BL(buf);
        int ng = wn * 32;
        #pragma unroll
        for (int ks = 0; ks < 2; ks++) {
            int kb = ks * 32;
            uint32_t ah0[4], ah1[4], al0[4], al1[4];
            ldsm4(ah0, sb + AHp + (m0 + laneA_row) * 80 + kb + laneA_koff);
            ldsm4(ah1, sb + AHp + (m0 + 16 + laneA_row) * 80 + kb + laneA_koff);
            ldsm4(al0, sb + ALp + (m0 + laneA_row) * 80 + kb + laneA_koff);
            ldsm4(al1, sb + ALp + (m0 + 16 + laneA_row) * 80 + kb + laneA_koff);
            uint32_t bh0[4], bh1[4], bl0[4], bl1[4];
            ldsm4(bh0, sb + BHp + (ng + laneB_nrow) * 80 + kb + laneB_koff);
            ldsm4(bh1, sb + BHp + (ng + 16 + laneB_nrow) * 80 + kb + laneB_koff);
            mma16816(c1[0][0], ah0, bh0[0], bh0[1]);
            mma16816(c1[0][1], ah0, bh0[2], bh0[3]);
            mma16816(c1[0][2], ah0, bh1[0], bh1[1]);
            mma16816(c1[0][3], ah0, bh1[2], bh1[3]);
            mma16816(c1[1][0], ah1, bh0[0], bh0[1]);
            mma16816(c1[1][1], ah1, bh0[2], bh0[3]);
            mma16816(c1[1][2], ah1, bh1[0], bh1[1]);
            mma16816(c1[1][3], ah1, bh1[2], bh1[3]);
            ldsm4(bl0, sb + BLp + (ng + laneB_nrow) * 80 + kb + laneB_koff);
            ldsm4(bl1, sb + BLp + (ng + 16 + laneB_nrow) * 80 + kb + laneB_koff);
            mma16816(c1[0][0], ah0, bl0[0], bl0[1]);
            mma16816(c1[0][1], ah0, bl0[2], bl0[3]);
            mma16816(c1[0][2], ah0, bl1[0], bl1[1]);
            mma16816(c1[0][3], ah0, bl1[2], bl1[3]);
            mma16816(c1[1][0], ah1, bl0[0], bl0[1]);
            mma16816(c1[1][1], ah1, bl0[2], bl0[3]);
            mma16816(c1[1][2], ah1, bl1[0], bl1[1]);
            mma16816(c1[1][3], ah1, bl1[2], bl1[3]);
            mma16816(c1[0][0], al0, bh0[0], bh0[1]);
            mma16816(c1[0][1], al0, bh0[2], bh0[3]);
            mma16816(c1[0][2], al0, bh1[0], bh1[1]);
            mma16816(c1[0][3], al0, bh1[2], bh1[3]);
            mma16816(c1[1][0], al1, bh0[0], bh0[1]);
            mma16816(c1[1][1], al1, bh0[2], bh0[3]);
            mma16816(c1[1][2], al1, bh1[0], bh1[1]);
            mma16816(c1[1][3], al1, bh1[2], bh1[3]);
        }
    }

    // epilogue: bias + gelu -> global h hi/lo
    {
        #pragma unroll
        for (int j = 0; j < 4; j++) {
            int ncol = wn * 32 + j * 8 + (lane & 3) * 2;
            int gcol = nsplit * 128 + ncol;
            float2 bb = *(const float2*)(b1 + gcol);
            #pragma unroll
            for (int i = 0; i < 2; i++) {
                int r0 = m0 + i * 16 + (lane >> 2);
                size_t gr0 = (hoff + base + r0) * HH + gcol;
                size_t gr1 = (hoff + base + r0 + 8) * HH + gcol;
                float h0 = gelu_exact(c1[i][j][0] + bb.x);
                float h1 = gelu_exact(c1[i][j][1] + bb.y);
                *(uint32_t*)(g_hh + gr0) = bfpack(h0, h1);
                *(uint32_t*)(g_hl + gr0) = bfpack(bfres(h0), bfres(h1));
                float h2 = gelu_exact(c1[i][j][2] + bb.x);
                float h3 = gelu_exact(c1[i][j][3] + bb.y);
                *(uint32_t*)(g_hh + gr1) = bfpack(h2, h3);
                *(uint32_t*)(g_hl + gr1) = bfpack(bfres(h2), bfres(h3));
            }
        }
    }
}

// ---------------- GEMM2: y = h @ W2 + b2; residual + LN ----------------
__global__ __launch_bounds__(NT2, 2)
void gemm2_kernel(int lvl,
                  const int* __restrict__ lvl_idx,
                  const int* __restrict__ lc, const int* __restrict__ rc,
                  const int* __restrict__ tcld,
                  const __nv_bfloat16* __restrict__ W2bTh, const __nv_bfloat16* __restrict__ W2bTl,
                  const __nv_bfloat16* __restrict__ W2tTh, const __nv_bfloat16* __restrict__ W2tTl,
                  const float* __restrict__ b2b, const float* __restrict__ b2t,
                  const float* __restrict__ gma, const float* __restrict__ bta,
                  float* __restrict__ final_out) {
    extern __shared__ char smem[];
    int bx = blockIdx.x;
    int tern = (bx & 1) ? 0 : 1;
    int tile = bx >> 1;
    int slot = lvl * 2 + (tern ? 0 : 1);
    int cnt = g_cnt[slot];
    int base = tile * MR2;
    if (base >= cnt) return;

    const __nv_bfloat16* WTh = tern ? W2tTh : W2bTh;
    const __nv_bfloat16* WTl = tern ? W2tTl : W2bTl;
    const float* b2 = tern ? b2t : b2b;
    size_t hoff = (size_t)(tern ? 0 : MAX_LVL);

    int t = threadIdx.x;
    int lane = t & 31, wid = t >> 5;
    uint32_t sb = (uint32_t)__cvta_generic_to_shared(smem);

    uint64_t* sm_ptrf = (uint64_t*)(smem + G2_PTRF);
    int* sm_node  = (int*)(smem + G2_NODE);
    int* sm_idx   = (int*)(smem + G2_IDX);
    int* sm_valid = (int*)(smem + G2_VALID);
    float* sm_mu  = (float*)(smem + G2_MU);
    float* sm_rs  = (float*)(smem + G2_RS);

    const int* rows = g_list[slot];
    if (t < MR2) {
        int rr = min(base + t, cnt - 1);
        int i = rows[rr];
        int node = lvl_idx[i];
        sm_node[t] = node;
        sm_idx[t] = i;
        sm_valid[t] = (base + t < cnt) ? 1 : 0;
        size_t lo_ = (size_t)lc[node] * D;
        size_t ro_ = (size_t)rc[node] * D;
        size_t to_ = tern ? (size_t)tcld[node] * D : lo_;
        sm_ptrf[t * 4 + 1] = (uint64_t)(g_embeds + lo_);
        sm_ptrf[t * 4 + 2] = (uint64_t)(g_embeds + ro_);
        sm_ptrf[t * 4 + 3] = (uint64_t)(g_embeds + to_);
    }
    __syncthreads();

    int wm = wid & 1, wn = wid >> 1;
    int m0 = wm * 32;
    int laneA_row  = lane & 15;
    int laneA_koff = (lane >> 4) * 16;
    int laneB_nrow = (lane & 7) + ((lane & 16) >> 1);
    int laneB_koff = ((lane >> 3) & 1) * 16;

    int a_row = t >> 2, a_q = t & 3;

    float c2[2][8][4];
    #pragma unroll
    for (int i = 0; i < 2; i++)
        #pragma unroll
        for (int j = 0; j < 8; j++)
            #pragma unroll
            for (int r = 0; r < 4; r++) c2[i][j][r] = 0.0f;

    // prologue chunk 0
    {
        const char* srcH = (const char*)(g_hh + (hoff + base + a_row) * HH) + a_q * 16;
        const char* srcL = (const char*)(g_hl + (hoff + base + a_row) * HH) + a_q * 16;
        cpasync16(sb + G2_AH(0) + a_row * 80 + a_q * 16, srcH);
        cpasync16(sb + G2_AL(0) + a_row * 80 + a_q * 16, srcL);
        const char* wsH = (const char*)(WTh + (size_t)t * HH);
        const char* wsL = (const char*)(WTl + (size_t)t * HH);
        uint32_t eH = sb + G2_BH(0) + t * 80;
        uint32_t eL = sb + G2_BL(0) + t * 80;
        #pragma unroll
        for (int j = 0; j < 4; j++) cpasync16(eH + j * 16, wsH + j * 16);
        #pragma unroll
        for (int j = 0; j < 4; j++) cpasync16(eL + j * 16, wsL + j * 16);
        CP_COMMIT();
    }
    for (int kc = 0; kc < 16; kc++) {
        CP_WAIT0();
        __syncthreads();
        if (kc + 1 < 16) {
            int buf = (kc + 1) & 1;
            int k0 = (kc + 1) * 32;
            const char* srcH = (const char*)(g_hh + (hoff + base + a_row) * HH + k0) + a_q * 16;
            const char* srcL = (const char*)(g_hl + (hoff + base + a_row) * HH + k0) + a_q * 16;
            cpasync16(sb + G2_AH(buf) + a_row * 80 + a_q * 16, srcH);
            cpasync16(sb + G2_AL(buf) + a_row * 80 + a_q * 16, srcL);
            const char* wsH = (const char*)(WTh + (size_t)t * HH + k0);
            const char* wsL = (const char*)(WTl + (size_t)t * HH + k0);
            uint32_t eH = sb + G2_BH(buf) + t * 80;
            uint32_t eL = sb + G2_BL(buf) + t * 80;
            #pragma unroll
            for (int j = 0; j < 4; j++) cpasync16(eH + j * 16, wsH + j * 16);
            #pragma unroll
            for (int j = 0; j < 4; j++) cpasync16(eL + j * 16, wsL + j * 16);
            CP_COMMIT();
        }
        int buf = kc & 1;
        uint32_t AHp = G2_AH(buf), ALp = G2_AL(buf), BHp = G2_BH(buf), BLp = G2_BL(buf);
        #pragma unroll
        for (int ks = 0; ks < 2; ks++) {
            int kb = ks * 32;
            uint32_t ah0[4], ah1[4], al0[4], al1[4];
            ldsm4(ah0, sb + AHp + (m0 + laneA_row) * 80 + kb + laneA_koff);
            ldsm4(ah1, sb + AHp + (m0 + 16 + laneA_row) * 80 + kb + laneA_koff);
            ldsm4(al0, sb + ALp + (m0 + laneA_row) * 80 + kb + laneA_koff);
            ldsm4(al1, sb + ALp + (m0 + 16 + laneA_row) * 80 + kb + laneA_koff);
            #pragma unroll
            for (int g = 0; g < 2; g++) {
                int ng = wn * 64 + g * 32;
                int jb = g * 4;
                uint32_t bh0[4], bh1[4], bl0[4], bl1[4];
                ldsm4(bh0, sb + BHp + (ng + laneB_nrow) * 80 + kb + laneB_koff);
                ldsm4(bh1, sb + BHp + (ng + 16 + laneB_nrow) * 80 + kb + laneB_koff);
                mma16816(c2[0][jb + 0], ah0, bh0[0], bh0[1]);
                mma16816(c2[0][jb + 1], ah0, bh0[2], bh0[3]);
                mma16816(c2[0][jb + 2], ah0, bh1[0], bh1[1]);
                mma16816(c2[0][jb + 3], ah0, bh1[2], bh1[3]);
                mma16816(c2[1][jb + 0], ah1, bh0[0], bh0[1]);
                mma16816(c2[1][jb + 1], ah1, bh0[2], bh0[3]);
                mma16816(c2[1][jb + 2], ah1, bh1[0], bh1[1]);
                mma16816(c2[1][jb + 3], ah1, bh1[2], bh1[3]);
                ldsm4(bl0, sb + BLp + (ng + laneB_nrow) * 80 + kb + laneB_koff);
                ldsm4(bl1, sb + BLp + (ng + 16 + laneB_nrow) * 80 + kb + laneB_koff);
                mma16816(c2[0][jb + 0], ah0, bl0[0], bl0[1]);
                mma16816(c2[0][jb + 1], ah0, bl0[2], bl0[3]);
                mma16816(c2[0][jb + 2], ah0, bl1[0], bl1[1]);
                mma16816(c2[0][jb + 3], ah0, bl1[2], bl1[3]);
                mma16816(c2[1][jb + 0], ah1, bl0[0], bl0[1]);
                mma16816(c2[1][jb + 1], ah1, bl0[2], bl0[3]);
                mma16816(c2[1][jb + 2], ah1, bl1[0], bl1[1]);
                mma16816(c2[1][jb + 3], ah1, bl1[2], bl1[3]);
                mma16816(c2[0][jb + 0], al0, bh0[0], bh0[1]);
                mma16816(c2[0][jb + 1], al0, bh0[2], bh0[3]);
                mma16816(c2[0][jb + 2], al0, bh1[0], bh1[1]);
                mma16816(c2[0][jb + 3], al0, bh1[2], bh1[3]);
                mma16816(c2[1][jb + 0], al1, bh0[0], bh0[1]);
                mma16816(c2[1][jb + 1], al1, bh0[2], bh0[3]);
                mma16816(c2[1][jb + 2], al1, bh1[0], bh1[1]);
                mma16816(c2[1][jb + 3], al1, bh1[2], bh1[3]);
            }
        }
    }
    __syncthreads();

    // epilogue: bias + residual -> zbuf
    {
        #pragma unroll
        for (int i = 0; i < 2; i++) {
            #pragma unroll
            for (int rh = 0; rh < 2; rh++) {
                int m = m0 + i * 16 + rh * 8 + (lane >> 2);
                const float* lp = (const float*)sm_ptrf[m * 4 + 1];
                const float* rp = (const float*)sm_ptrf[m * 4 + 2];
                const float* tp = (const float*)sm_ptrf[m * 4 + 3];
                #pragma unroll
                for (int j = 0; j < 8; j++) {
                    int n = wn * 64 + j * 8 + (lane & 3) * 2;
                    float2 bv = *(const float2*)(b2 + n);
                    float y0 = c2[i][j][rh * 2]     + bv.x;
                    float y1 = c2[i][j][rh * 2 + 1] + bv.y;
                    float2 lv = *(const float2*)(lp + n);
                    float2 rv = *(const float2*)(rp + n);
                    if (tern) {
                        float2 tv = *(const float2*)(tp + n);
                        y0 += (lv.x + rv.x + tv.x) * (1.0f / 3.0f);
                        y1 += (lv.y + rv.y + tv.y) * (1.0f / 3.0f);
                    } else {
                        y0 += lv.x + rv.x;
                        y1 += lv.y + rv.y;
                    }
                    *(float2*)(smem + G2_PZ + m * 1040 + n * 4) = make_float2(y0, y1);
                }
            }
        }
    }
    __syncthreads();

    if (t < MR2) {
        const float* zr = (const float*)(smem + G2_PZ + t * 1040);
        float s = 0.0f, s2 = 0.0f;
        #pragma unroll 8
        for (int c = 0; c < D; c++) {
            float v = zr[c];
            s += v;
            s2 += v * v;
        }
        float mu = s * (1.0f / 256.0f);
        float var = s2 * (1.0f / 256.0f) - mu * mu;
        sm_mu[t] = mu;
        sm_rs[t] = rsqrtf(var + 1e-5f);
    }
    __syncthreads();

    for (int idx = t; idx < MR2 * 64; idx += NT2) {
        int row = idx >> 6, q = idx & 63;
        if (!sm_valid[row]) continue;
        float mu = sm_mu[row], rs = sm_rs[row];
        const float* zr = (const float*)(smem + G2_PZ + row * 1040) + q * 4;
        float4 g4 = *(const float4*)(gma + q * 4);
        float4 be = *(const float4*)(bta + q * 4);
        float4 o;
        o.x = (zr[0] - mu) * rs * g4.x + be.x;
        o.y = (zr[1] - mu) * rs * g4.y + be.y;
        o.z = (zr[2] - mu) * rs * g4.z + be.z;
        o.w = (zr[3] - mu) * rs * g4.w + be.w;
        if (final_out) {
            *(float4*)(final_out + (size_t)sm_idx[row] * D + q * 4) = o;
        } else {
            size_t off = (size_t)sm_node[row] * D + q * 4;
            *(float4*)(g_embeds + off) = o;
            uint2 hv, lv;
            hv.x = bfpack(o.x, o.y);
            hv.y = bfpack(o.z, o.w);
            lv.x = bfpack(bfres(o.x), bfres(o.y));
            lv.y = bfpack(bfres(o.z), bfres(o.w));
            *(uint2*)(g_embh + off) = hv;
            *(uint2*)(g_embl + off) = lv;
        }
    }
}

// ---------------- launcher ----------------
extern "C" void kernel_launch(void* const* d_in, const int* in_sizes, int n_in,
                              void* d_out, int out_size) {
    const int*   comp_ids   = (const int*)d_in[0];
    const int*   op_ids     = (const int*)d_in[1];
    const int*   lc         = (const int*)d_in[2];
    const int*   rc         = (const int*)d_in[3];
    const int*   tc         = (const int*)d_in[4];
    const int*   l2         = (const int*)d_in[5];
    const int*   l1         = (const int*)d_in[6];
    const int*   l0         = (const int*)d_in[7];
    const float* comp_table = (const float*)d_in[8];
    const float* op_table   = (const float*)d_in[9];
    const float* W1b        = (const float*)d_in[10];
    const float* b1b        = (const float*)d_in[11];
    const float* W2b        = (const float*)d_in[12];
    const float* b2b        = (const float*)d_in[13];
    const float* W1t        = (const float*)d_in[14];
    const float* b1t        = (const float*)d_in[15];
    const float* W2t        = (const float*)d_in[16];
    const float* b2t        = (const float*)d_in[17];
    const float* gma        = (const float*)d_in[18];
    const float* bta        = (const float*)d_in[19];

    int n_nodes = in_sizes[0];
    int n2 = in_sizes[5], n1 = in_sizes[6], n0 = in_sizes[7];

    cudaFuncSetAttribute(gemm1_kernel, cudaFuncAttributeMaxDynamicSharedMemorySize, G1_SMEM);
    cudaFuncSetAttribute(gemm2_kernel, cudaFuncAttributeMaxDynamicSharedMemorySize, G2_SMEM);

    __nv_bfloat16 *w1bh, *w1bl, *w1th, *w1tl, *w2bh, *w2bl, *w2th, *w2tl;
    cudaGetSymbolAddress((void**)&w1bh, g_W1bTh);
    cudaGetSymbolAddress((void**)&w1bl, g_W1bTl);
    cudaGetSymbolAddress((void**)&w1th, g_W1tTh);
    cudaGetSymbolAddress((void**)&w1tl, g_W1tTl);
    cudaGetSymbolAddress((void**)&w2bh, g_W2bTh);
    cudaGetSymbolAddress((void**)&w2bl, g_W2bTl);
    cudaGetSymbolAddress((void**)&w2th, g_W2tTh);
    cudaGetSymbolAddress((void**)&w2tl, g_W2tTl);

    dim3 tb(32, 8);
    convall_kernel<<<1152, tb>>>(W1b, W1t, W2b, W2t);
    init_all_kernel<<<n_nodes + 16, D>>>(comp_ids, comp_table, op_table, n_nodes);
    int tot = n2 + n1 + n0;
    compact_kernel<<<(tot + 255) / 256, 256>>>(l2, n2, l1, n1, l0, n0, tc);

    int ns[3] = {n2, n1, n0};
    const int* lidx[3] = {l2, l1, l0};
    for (int lvl = 0; lvl < 3; lvl++) {
        int nb1 = (ns[lvl] + MR1 - 1) / MR1;
        int nb2 = (ns[lvl] + MR2 - 1) / MR2;
        float* fout = (lvl == 2) ? (float*)d_out : nullptr;
        gemm1_kernel<<<nb1 * 8, NT1, G1_SMEM>>>(
            lvl, lidx[lvl], lc, rc, tc, op_ids,
            w1bh, w1bl, w1th, w1tl, b1b, b1t);
        gemm2_kernel<<<nb2 * 2, NT2, G2_SMEM>>>(
            lvl, lidx[lvl], lc, rc, tc,
            w2bh, w2bl, w2th, w2tl, b2b, b2t, gma, bta, fout);
    }
}